// round 5
// baseline (speedup 1.0000x reference)
#include <cuda_runtime.h>
#include <cuda_bf16.h>
#include <math.h>
#include <stdint.h>

// Problem dims
#define BB 64
#define SS 50
#define EE 512
#define HH 1024
#define VTS 32000
#define NSTEP 49
#define MPROJ (NSTEP*BB)   /* 3136 */
#define MPAD  3200
#define G4H 4096
#define KSPLIT 8
#define KCHUNK 128         /* 1024/8 */
#define KCAT 3072          /* 3-term concat K */

typedef unsigned long long ull;

// ---------- packed f32x2 helpers ----------
__device__ __forceinline__ ull dup2(float x){
    ull r; asm("mov.b64 %0, {%1, %1};" : "=l"(r) : "f"(x)); return r;
}
__device__ __forceinline__ void ffma2(ull &d, ull a, ull b){
    asm("fma.rn.f32x2 %0, %1, %2, %0;" : "+l"(d) : "l"(a), "l"(b));
}
__device__ __forceinline__ float2 unpk(ull v){
    float2 f; asm("mov.b64 {%0, %1}, %2;" : "=f"(f.x), "=f"(f.y) : "l"(v)); return f;
}

// ---------- baseline-PTX tensor helpers (no 'a'-target features) ----------
__device__ __forceinline__ uint32_t smem_u32(const void* p){
    uint32_t a;
    asm("{ .reg .u64 t; cvta.to.shared.u64 t, %1; cvt.u32.u64 %0, t; }" : "=r"(a) : "l"(p));
    return a;
}
__device__ __forceinline__ void cpasync16(uint32_t dst, const void* src){
    asm volatile("cp.async.cg.shared.global [%0], [%1], 16;" :: "r"(dst), "l"(src));
}
__device__ __forceinline__ void cp_commit(){
    asm volatile("cp.async.commit_group;");
}
__device__ __forceinline__ void ldm4(uint32_t* r, uint32_t a){
    asm volatile("ldmatrix.sync.aligned.m8n8.x4.shared.b16 {%0,%1,%2,%3}, [%4];"
        : "=r"(r[0]), "=r"(r[1]), "=r"(r[2]), "=r"(r[3]) : "r"(a));
}
__device__ __forceinline__ void mma16816(float* c, const uint32_t* a, uint32_t b0, uint32_t b1){
    asm volatile("mma.sync.aligned.m16n8k16.row.col.f32.bf16.bf16.f32 "
        "{%0,%1,%2,%3}, {%4,%5,%6,%7}, {%8,%9}, {%0,%1,%2,%3};"
        : "+f"(c[0]), "+f"(c[1]), "+f"(c[2]), "+f"(c[3])
        : "r"(a[0]), "r"(a[1]), "r"(a[2]), "r"(a[3]), "r"(b0), "r"(b1));
}

// ---------- scratch ----------
__device__ float g_enc_out[BB*SS*EE];
__device__ float g_avg[BB*EE];
__device__ float g_ctx[BB*EE];
__device__ float g_h[BB*HH];
__device__ float g_c[BB*HH];
__device__ float g_gconst[BB*G4H];
__device__ float g_part[KSPLIT*BB*G4H];
__device__ float g_pre[MPAD*G4H];                    // per-step const gate input
__device__ __nv_bfloat16 g_Acat[(size_t)MPAD*KCAT];  // [Ah|Ah|Al] rows (zero beyond 3136)
__device__ __nv_bfloat16 g_Bcat[(size_t)VTS*KCAT];   // [Bh|Bl|Bh] rows

// ============================================================
// Encoder GEMM (fp32 FFMA2) — unchanged from round 1
// ============================================================
__global__ __launch_bounds__(256)
void enc_gemm(const int* __restrict__ src, const int* __restrict__ pos,
              const float* __restrict__ enc_emb, const float* __restrict__ pos_emb,
              const float* __restrict__ cat_W, const float* __restrict__ cat_b)
{
    __shared__ __align__(16) float As[128*20];
    __shared__ __align__(16) float Bs[16*132];
    const int m0 = blockIdx.x * 128;
    const int n0 = blockIdx.y * 128;
    const int tid = threadIdx.x;
    const int tx = tid & 15, ty = tid >> 4;

    ull acc[8][2][2];
    #pragma unroll
    for (int i=0;i<8;i++)
        #pragma unroll
        for (int q=0;q<2;q++){ acc[i][q][0]=0ull; acc[i][q][1]=0ull; }

    for (int kt = 0; kt < 1024; kt += 16){
        #pragma unroll
        for (int l=0;l<2;l++){
            int f4 = tid + 256*l;
            int row = f4 >> 2, k4 = (f4 & 3) << 2;
            int kg = kt + k4;
            int r = m0 + row;
            float4 v;
            if (kg < 512) v = *(const float4*)(enc_emb + (size_t)src[r]*512 + kg);
            else          v = *(const float4*)(pos_emb + (size_t)pos[r]*512 + (kg - 512));
            *(float4*)(As + row*20 + k4) = v;
        }
        #pragma unroll
        for (int l=0;l<2;l++){
            int f4 = tid + 256*l;
            int row = f4 >> 2, k4 = (f4 & 3) << 2;
            float4 v = *(const float4*)(cat_W + (size_t)(n0+row)*1024 + kt + k4);
            Bs[(k4+0)*132 + row] = v.x;
            Bs[(k4+1)*132 + row] = v.y;
            Bs[(k4+2)*132 + row] = v.z;
            Bs[(k4+3)*132 + row] = v.w;
        }
        __syncthreads();
        #pragma unroll
        for (int kq=0;kq<4;kq++){
            float4 av[8];
            #pragma unroll
            for (int i=0;i<8;i++) av[i] = *(const float4*)(As + (ty*8+i)*20 + kq*4);
            #pragma unroll
            for (int kk=0;kk<4;kk++){
                ull a2[8];
                #pragma unroll
                for (int i=0;i<8;i++){
                    float a = (kk==0)?av[i].x:(kk==1)?av[i].y:(kk==2)?av[i].z:av[i].w;
                    a2[i] = dup2(a);
                }
                const int k = kq*4+kk;
                #pragma unroll
                for (int q=0;q<2;q++){
                    ulonglong2 bv = *(const ulonglong2*)(Bs + k*132 + tx*4 + q*64);
                    #pragma unroll
                    for (int i=0;i<8;i++){ ffma2(acc[i][q][0], a2[i], bv.x);
                                           ffma2(acc[i][q][1], a2[i], bv.y); }
                }
            }
        }
        __syncthreads();
    }
    #pragma unroll
    for (int i=0;i<8;i++){
        int gm = m0 + ty*8 + i;
        #pragma unroll
        for (int q=0;q<2;q++){
            int gn = n0 + tx*4 + q*64;
            float2 p0 = unpk(acc[i][q][0]);
            float2 p1 = unpk(acc[i][q][1]);
            float4 bb = *(const float4*)(cat_b + gn);
            *(float4*)(g_enc_out + (size_t)gm*512 + gn) =
                make_float4(p0.x+bb.x, p0.y+bb.y, p1.x+bb.z, p1.y+bb.w);
        }
    }
}

__global__ void avg_kernel()
{
    int b = blockIdx.x, e = threadIdx.x;
    float s = 0.f;
    #pragma unroll 5
    for (int si=0; si<SS; si++) s += g_enc_out[(b*SS+si)*EE + e];
    g_avg[b*EE + e] = s * (1.0f/50.0f);
}

__global__ void h0_kernel(const float* __restrict__ scale_W, const float* __restrict__ scale_b)
{
    int gid = blockIdx.x*blockDim.x + threadIdx.x;
    int b = gid >> 10, h = gid & 1023;
    const float4* a = (const float4*)(g_avg + b*EE);
    const float4* w = (const float4*)(scale_W + (size_t)h*EE);
    float s = 0.f;
    #pragma unroll 8
    for (int i=0;i<128;i++){
        float4 av=a[i], wv=w[i];
        s += av.x*wv.x + av.y*wv.y + av.z*wv.z + av.w*wv.w;
    }
    float v = fmaxf(s + scale_b[h], 0.f);
    g_h[gid] = v; g_c[gid] = v;
}

__global__ void attn_kernel(const float* __restrict__ attn_W, const int* __restrict__ src)
{
    int b = blockIdx.x, tid = threadIdx.x;
    __shared__ float sc[56];
    __shared__ float aw[56];
    int w = tid >> 5, lane = tid & 31;
    for (int s = w; s < SS; s += 8){
        const float* row = g_enc_out + (size_t)(b*SS+s)*EE;
        float a = 0.f;
        for (int e = lane; e < EE; e += 32) a += row[e]*attn_W[e];
        #pragma unroll
        for (int o=16;o>0;o>>=1) a += __shfl_xor_sync(0xffffffffu, a, o);
        if (lane==0) sc[s] = a;
    }
    __syncthreads();
    if (tid == 0){
        float mx = -1e30f;
        for (int s=0;s<SS;s++) mx = fmaxf(mx, sc[s]);
        float tot = 0.f;
        for (int s=0;s<SS;s++){
            float e = (src[b*SS+s]==0) ? 0.f : expf(sc[s]-mx);
            aw[s] = e; tot += e;
        }
        float inv = 1.f/tot;
        for (int s=0;s<SS;s++) aw[s] *= inv;
    }
    __syncthreads();
    for (int e = tid; e < EE; e += blockDim.x){
        float a = 0.f;
        #pragma unroll 5
        for (int s=0;s<SS;s++) a += aw[s]*g_enc_out[(size_t)(b*SS+s)*EE + e];
        g_ctx[b*EE + e] = a;
    }
}

__global__ void gconst_kernel(const float* __restrict__ W_ih,
                              const float* __restrict__ b_ih, const float* __restrict__ b_hh)
{
    int gid = blockIdx.x*blockDim.x + threadIdx.x;
    int b = gid >> 12, j = gid & 4095;
    const float4* c4 = (const float4*)(g_ctx + b*EE);
    const float4* w4 = (const float4*)(W_ih + (size_t)j*1024 + 512);
    float s = 0.f;
    #pragma unroll 8
    for (int i=0;i<128;i++){
        float4 cv=c4[i], wv=w4[i];
        s += cv.x*wv.x + cv.y*wv.y + cv.z*wv.z + cv.w*wv.w;
    }
    g_gconst[gid] = s + b_ih[j] + b_hh[j];
}

// ============================================================
// Hoisted token-embedding GEMM for ALL steps:
// pre[r=t*64+b, j] = dec_emb[tok[b,t]] . W_ih[j,0:512] + gconst[b,j]
// M=3200, N=4096, K=512 (fp32 FFMA2)
// ============================================================
__global__ __launch_bounds__(256)
void dec_pre(const int* __restrict__ tgt, const float* __restrict__ dec_emb,
             const float* __restrict__ W_ih)
{
    __shared__ __align__(16) float As[128*20];
    __shared__ __align__(16) float Bs[16*132];
    const int m0 = blockIdx.x * 128;
    const int n0 = blockIdx.y * 128;
    const int tid = threadIdx.x;
    const int tx = tid & 15, ty = tid >> 4;

    ull acc[8][2][2];
    #pragma unroll
    for (int i=0;i<8;i++)
        #pragma unroll
        for (int q=0;q<2;q++){ acc[i][q][0]=0ull; acc[i][q][1]=0ull; }

    for (int kt = 0; kt < 512; kt += 16){
        #pragma unroll
        for (int l=0;l<2;l++){
            int f4 = tid + 256*l;
            int row = f4 >> 2, k4 = (f4 & 3) << 2;
            int r = m0 + row;
            int tok = tgt[(r & 63)*50 + (r >> 6)];
            float4 v = *(const float4*)(dec_emb + (size_t)tok*512 + kt + k4);
            *(float4*)(As + row*20 + k4) = v;
        }
        #pragma unroll
        for (int l=0;l<2;l++){
            int f4 = tid + 256*l;
            int row = f4 >> 2, k4 = (f4 & 3) << 2;
            float4 v = *(const float4*)(W_ih + (size_t)(n0+row)*1024 + kt + k4);
            Bs[(k4+0)*132 + row] = v.x;
            Bs[(k4+1)*132 + row] = v.y;
            Bs[(k4+2)*132 + row] = v.z;
            Bs[(k4+3)*132 + row] = v.w;
        }
        __syncthreads();
        #pragma unroll
        for (int kq=0;kq<4;kq++){
            float4 av[8];
            #pragma unroll
            for (int i=0;i<8;i++) av[i] = *(const float4*)(As + (ty*8+i)*20 + kq*4);
            #pragma unroll
            for (int kk=0;kk<4;kk++){
                ull a2[8];
                #pragma unroll
                for (int i=0;i<8;i++){
                    float a = (kk==0)?av[i].x:(kk==1)?av[i].y:(kk==2)?av[i].z:av[i].w;
                    a2[i] = dup2(a);
                }
                const int k = kq*4+kk;
                #pragma unroll
                for (int q=0;q<2;q++){
                    ulonglong2 bv = *(const ulonglong2*)(Bs + k*132 + tx*4 + q*64);
                    #pragma unroll
                    for (int i=0;i<8;i++){ ffma2(acc[i][q][0], a2[i], bv.x);
                                           ffma2(acc[i][q][1], a2[i], bv.y); }
                }
            }
        }
        __syncthreads();
    }
    #pragma unroll
    for (int i=0;i<8;i++){
        int gm = m0 + ty*8 + i;
        int b = gm & 63;
        #pragma unroll
        for (int q=0;q<2;q++){
            int gn = n0 + tx*4 + q*64;
            float2 p0 = unpk(acc[i][q][0]);
            float2 p1 = unpk(acc[i][q][1]);
            float4 gc = *(const float4*)(g_gconst + (size_t)b*G4H + gn);
            *(float4*)(g_pre + (size_t)gm*G4H + gn) =
                make_float4(p0.x+gc.x, p0.y+gc.y, p1.x+gc.z, p1.y+gc.w);
        }
    }
}

// ============================================================
// Per-step gates GEMM (split-K over K=1024): part = h . W_hh^T
// ============================================================
__global__ __launch_bounds__(128)
void gates_gemm(const float* __restrict__ W_hh)
{
    __shared__ __align__(16) float As[64*20];
    __shared__ __align__(16) float Bs[16*132];
    const int n0 = blockIdx.x * 128;
    const int kbase = blockIdx.y * KCHUNK;
    const int tid = threadIdx.x;
    const int tx = tid & 15, ty = tid >> 4;

    ull acc[8][2][2];
    #pragma unroll
    for (int i=0;i<8;i++)
        #pragma unroll
        for (int q=0;q<2;q++){ acc[i][q][0]=0ull; acc[i][q][1]=0ull; }

    for (int kt = 0; kt < KCHUNK; kt += 16){
        const int kg0 = kbase + kt;
        #pragma unroll
        for (int l=0;l<2;l++){
            int f4 = tid + 128*l;
            int row = f4 >> 2, k4 = (f4 & 3) << 2;
            float4 v = *(const float4*)(g_h + row*1024 + kg0 + k4);
            *(float4*)(As + row*20 + k4) = v;
        }
        #pragma unroll
        for (int l=0;l<4;l++){
            int f4 = tid + 128*l;
            int row = f4 >> 2, k4 = (f4 & 3) << 2;
            float4 v = *(const float4*)(W_hh + (size_t)(n0+row)*1024 + kg0 + k4);
            Bs[(k4+0)*132 + row] = v.x;
            Bs[(k4+1)*132 + row] = v.y;
            Bs[(k4+2)*132 + row] = v.z;
            Bs[(k4+3)*132 + row] = v.w;
        }
        __syncthreads();
        #pragma unroll
        for (int kq=0;kq<4;kq++){
            float4 av[8];
            #pragma unroll
            for (int i=0;i<8;i++) av[i] = *(const float4*)(As + (ty*8+i)*20 + kq*4);
            #pragma unroll
            for (int kk=0;kk<4;kk++){
                ull a2[8];
                #pragma unroll
                for (int i=0;i<8;i++){
                    float a = (kk==0)?av[i].x:(kk==1)?av[i].y:(kk==2)?av[i].z:av[i].w;
                    a2[i] = dup2(a);
                }
                const int k = kq*4+kk;
                #pragma unroll
                for (int q=0;q<2;q++){
                    ulonglong2 bv = *(const ulonglong2*)(Bs + k*132 + tx*4 + q*64);
                    #pragma unroll
                    for (int i=0;i<8;i++){ ffma2(acc[i][q][0], a2[i], bv.x);
                                           ffma2(acc[i][q][1], a2[i], bv.y); }
                }
            }
        }
        __syncthreads();
    }
    float* outp = g_part + (size_t)blockIdx.y*(BB*G4H);
    #pragma unroll
    for (int i=0;i<8;i++){
        int m = ty*8 + i;
        #pragma unroll
        for (int q=0;q<2;q++){
            int n = n0 + tx*4 + q*64;
            float2 p0 = unpk(acc[i][q][0]);
            float2 p1 = unpk(acc[i][q][1]);
            *(float4*)(outp + (size_t)m*G4H + n) = make_float4(p0.x, p0.y, p1.x, p1.y);
        }
    }
}

// ============================================================
// LSTM pointwise; emits h rows into A' = [Ah | Ah | Al]
// ============================================================
__global__ void lstm_pw(int t)
{
    int gid = blockIdx.x*blockDim.x + threadIdx.x;
    int b = gid >> 10, h = gid & 1023;
    size_t prow = (size_t)(t*64 + b)*G4H;
    float gi = g_pre[prow + h];
    float gf = g_pre[prow + 1024 + h];
    float gg = g_pre[prow + 2048 + h];
    float go = g_pre[prow + 3072 + h];
    int base = b*G4H;
    #pragma unroll
    for (int s=0;s<KSPLIT;s++){
        const float* p = g_part + (size_t)s*(BB*G4H) + base;
        gi += p[h]; gf += p[1024+h]; gg += p[2048+h]; go += p[3072+h];
    }
    float c  = g_c[gid];
    float ii = 1.f/(1.f+expf(-gi));
    float ff = 1.f/(1.f+expf(-gf));
    float oo = 1.f/(1.f+expf(-go));
    float gt = tanhf(gg);
    float cn = ff*c + ii*gt;
    float hn = oo*tanhf(cn);
    g_c[gid] = cn; g_h[gid] = hn;

    __nv_bfloat16 hhi = __float2bfloat16_rn(hn);
    float hif = __bfloat162float(hhi);
    __nv_bfloat16 hlo = __float2bfloat16_rn(hn - hif);
    size_t arow = (size_t)(t*64 + b)*KCAT;
    g_Acat[arow + h]        = hhi;
    g_Acat[arow + 1024 + h] = hhi;
    g_Acat[arow + 2048 + h] = hlo;
}

// ============================================================
// proj_W fp32 -> B' = [Bh | Bl | Bh] (bf16)
// ============================================================
__global__ __launch_bounds__(256)
void conv_w(const float* __restrict__ W)
{
    size_t i = (size_t)blockIdx.x*blockDim.x + threadIdx.x;   // 8,192,000 float4s
    int n = (int)(i >> 8);
    int k = (int)(i & 255) * 4;
    float4 v = ((const float4*)W)[i];
    __nv_bfloat16 h0 = __float2bfloat16_rn(v.x);
    __nv_bfloat16 h1 = __float2bfloat16_rn(v.y);
    __nv_bfloat16 h2 = __float2bfloat16_rn(v.z);
    __nv_bfloat16 h3 = __float2bfloat16_rn(v.w);
    __nv_bfloat16 l0 = __float2bfloat16_rn(v.x - __bfloat162float(h0));
    __nv_bfloat16 l1 = __float2bfloat16_rn(v.y - __bfloat162float(h1));
    __nv_bfloat16 l2 = __float2bfloat16_rn(v.z - __bfloat162float(h2));
    __nv_bfloat16 l3 = __float2bfloat16_rn(v.w - __bfloat162float(h3));
    ull hi, lo;
    asm("mov.b64 %0, {%1,%2,%3,%4};" : "=l"(hi)
        : "h"(*(unsigned short*)&h0), "h"(*(unsigned short*)&h1),
          "h"(*(unsigned short*)&h2), "h"(*(unsigned short*)&h3));
    asm("mov.b64 %0, {%1,%2,%3,%4};" : "=l"(lo)
        : "h"(*(unsigned short*)&l0), "h"(*(unsigned short*)&l1),
          "h"(*(unsigned short*)&l2), "h"(*(unsigned short*)&l3));
    size_t rb = (size_t)n*KCAT;
    *(ull*)(g_Bcat + rb + k)        = hi;
    *(ull*)(g_Bcat + rb + 1024 + k) = lo;
    *(ull*)(g_Bcat + rb + 2048 + k) = hi;
}

// ============================================================
// Projection via mma.sync bf16: out = A'(3200xK) . B'(32000xK)^T + bias
// CTA 128x128, 8 warps (4M x 2N), 3-stage cp.async pipeline, K=3072.
// smem rows padded to 80B -> conflict-free ldmatrix.
// ============================================================
#define NSTG 3
#define TSTAGE 10240            /* 128 rows * 80 B */
#define SM_PROJ (NSTG*2*TSTAGE) /* 61440 */

__global__ __launch_bounds__(256)
void proj_mma(float* __restrict__ out, const float* __restrict__ bias)
{
    extern __shared__ __align__(16) char sm[];
    const uint32_t uA = smem_u32(sm);
    const uint32_t uB = uA + NSTG*TSTAGE;
    const int tid = threadIdx.x;
    const int wid = tid >> 5, lane = tid & 31;
    const int m0 = blockIdx.x * 128;
    const int n0 = blockIdx.y * 128;
    const int wm = wid & 3, wn = wid >> 2;

    const int lrow = tid >> 2;            // 0..63
    const int lc   = (tid & 3);           // 16B chunk in 64B row

    float acc[2][8][4];
    #pragma unroll
    for (int a=0;a<2;a++)
        #pragma unroll
        for (int j=0;j<8;j++)
            #pragma unroll
            for (int x=0;x<4;x++) acc[a][j][x] = 0.f;

    const __nv_bfloat16* gA = g_Acat + (size_t)m0*KCAT;
    const __nv_bfloat16* gB = g_Bcat + (size_t)n0*KCAT;

    // ---- stage loader ----
    auto load_stage = [&](int slot, int ks){
        int k0 = ks * 32;
        #pragma unroll
        for (int half = 0; half < 2; half++){
            int row = lrow + half*64;
            cpasync16(uA + slot*TSTAGE + row*80 + lc*16,
                      gA + (size_t)row*KCAT + k0 + lc*8);
            cpasync16(uB + slot*TSTAGE + row*80 + lc*16,
                      gB + (size_t)row*KCAT + k0 + lc*8);
        }
        cp_commit();
    };

    load_stage(0, 0);
    load_stage(1, 1);

    const int g  = lane >> 3;     // ldmatrix tile group 0..3
    const int lr = lane & 7;

    for (int ks = 0; ks < 96; ks++){
        asm volatile("cp.async.wait_group 1;");
        __syncthreads();
        int ld = ks + NSTG - 1;
        if (ld < 96) load_stage(ld % NSTG, ld);
        else cp_commit();

        const uint32_t bufA = uA + (ks % NSTG)*TSTAGE;
        const uint32_t bufB = uB + (ks % NSTG)*TSTAGE;

        #pragma unroll
        for (int kk = 0; kk < 32; kk += 16){
            uint32_t afr[2][4];
            #pragma unroll
            for (int mi = 0; mi < 2; mi++){
                int row = wm*32 + mi*16 + ((g & 1) ? 8 : 0) + lr;
                int kof = kk + (g >> 1)*8;
                ldm4(afr[mi], bufA + row*80 + kof*2);
            }
            uint32_t bfr[4][4];
            #pragma unroll
            for (int p = 0; p < 4; p++){
                int row = wn*64 + p*16 + (g >> 1)*8 + lr;
                int kof = kk + (g & 1)*8;
                ldm4(bfr[p], bufB + row*80 + kof*2);
            }
            #pragma unroll
            for (int mi = 0; mi < 2; mi++)
                #pragma unroll
                for (int j = 0; j < 8; j++){
                    int p = j >> 1, h2 = (j & 1)*2;
                    mma16816(acc[mi][j], afr[mi], bfr[p][h2], bfr[p][h2+1]);
                }
        }
        __syncthreads();
    }

    // ---- epilogue ----
    const int tm = lane >> 2;
    const int tn = (lane & 3)*2;
    #pragma unroll
    for (int mi = 0; mi < 2; mi++){
        #pragma unroll
        for (int j = 0; j < 8; j++){
            int gn = n0 + wn*64 + j*8 + tn;
            float2 bb = *(const float2*)(bias + gn);
            int gm0 = m0 + wm*32 + mi*16 + tm;
            if (gm0 < MPROJ){
                float2 o; o.x = acc[mi][j][0] + bb.x; o.y = acc[mi][j][1] + bb.y;
                *(float2*)(out + (size_t)gm0*VTS + gn) = o;
            }
            int gm1 = gm0 + 8;
            if (gm1 < MPROJ){
                float2 o; o.x = acc[mi][j][2] + bb.x; o.y = acc[mi][j][3] + bb.y;
                *(float2*)(out + (size_t)gm1*VTS + gn) = o;
            }
        }
    }
}

// ============================================================
extern "C" void kernel_launch(void* const* d_in, const int* in_sizes, int n_in,
                              void* d_out, int out_size)
{
    const int*   src      = (const int*)  d_in[0];
    const int*   pos      = (const int*)  d_in[2];
    const int*   tgt      = (const int*)  d_in[3];
    const float* enc_emb  = (const float*)d_in[4];
    const float* pos_emb  = (const float*)d_in[5];
    const float* cat_W    = (const float*)d_in[6];
    const float* cat_b    = (const float*)d_in[7];
    const float* scale_W  = (const float*)d_in[8];
    const float* scale_b  = (const float*)d_in[9];
    const float* dec_emb  = (const float*)d_in[10];
    const float* attn_W   = (const float*)d_in[11];
    const float* W_ih     = (const float*)d_in[13];
    const float* W_hh     = (const float*)d_in[14];
    const float* b_ih     = (const float*)d_in[15];
    const float* b_hh     = (const float*)d_in[16];
    const float* proj_W   = (const float*)d_in[17];
    const float* proj_b   = (const float*)d_in[18];
    float* out = (float*)d_out;

    cudaFuncSetAttribute(proj_mma, cudaFuncAttributeMaxDynamicSharedMemorySize, SM_PROJ);

    // B' conversion (independent; overlaps encoder work in-order on stream)
    conv_w<<<32000, 256>>>(proj_W);

    // Encoder
    enc_gemm<<<dim3(25,4), 256>>>(src, pos, enc_emb, pos_emb, cat_W, cat_b);
    avg_kernel<<<64, 512>>>();
    h0_kernel<<<256, 256>>>(scale_W, scale_b);

    // Loop-invariant attention context + hoisted per-step constants
    attn_kernel<<<64, 256>>>(attn_W, src);
    gconst_kernel<<<1024, 256>>>(W_ih, b_ih, b_hh);
    dec_pre<<<dim3(25,32), 256>>>(tgt, dec_emb, W_ih);

    // Recurrence: only h . W_hh^T is sequential now (K=1024)
    for (int t = 0; t < NSTEP; t++){
        gates_gemm<<<dim3(32, KSPLIT), 128>>>(W_hh);
        lstm_pw<<<256, 256>>>(t);
    }

    // Tensor-core projection (single GEMM, K=3072 3-term concat)
    proj_mma<<<dim3(25,250), 256, SM_PROJ>>>(out, proj_b);
}

// round 6
// speedup vs baseline: 1.0033x; 1.0033x over previous
#include <cuda_runtime.h>
#include <cuda_bf16.h>
#include <math.h>
#include <stdint.h>

// Problem dims
#define BB 64
#define SS 50
#define EE 512
#define HH 1024
#define VTS 32000
#define NSTEP 49
#define MPROJ (NSTEP*BB)   /* 3136 */
#define MPAD  3200
#define G4H 4096
#define KSPLIT 8
#define KCHUNK 128         /* 1024/8 */
#define KCAT 3072          /* 3-term concat K */

typedef unsigned long long ull;

// ---------- packed f32x2 helpers ----------
__device__ __forceinline__ ull dup2(float x){
    ull r; asm("mov.b64 %0, {%1, %1};" : "=l"(r) : "f"(x)); return r;
}
__device__ __forceinline__ void ffma2(ull &d, ull a, ull b){
    asm("fma.rn.f32x2 %0, %1, %2, %0;" : "+l"(d) : "l"(a), "l"(b));
}
__device__ __forceinline__ float2 unpk(ull v){
    float2 f; asm("mov.b64 {%0, %1}, %2;" : "=f"(f.x), "=f"(f.y) : "l"(v)); return f;
}

// ---------- baseline-PTX tensor helpers (no 'a'-target features) ----------
__device__ __forceinline__ uint32_t smem_u32(const void* p){
    uint32_t a;
    asm("{ .reg .u64 t; cvta.to.shared.u64 t, %1; cvt.u32.u64 %0, t; }" : "=r"(a) : "l"(p));
    return a;
}
__device__ __forceinline__ void cpasync16(uint32_t dst, const void* src){
    asm volatile("cp.async.cg.shared.global [%0], [%1], 16;" :: "r"(dst), "l"(src));
}
__device__ __forceinline__ void cp_commit(){
    asm volatile("cp.async.commit_group;");
}
__device__ __forceinline__ void ldm4(uint32_t* r, uint32_t a){
    asm volatile("ldmatrix.sync.aligned.m8n8.x4.shared.b16 {%0,%1,%2,%3}, [%4];"
        : "=r"(r[0]), "=r"(r[1]), "=r"(r[2]), "=r"(r[3]) : "r"(a));
}
__device__ __forceinline__ void mma16816(float* c, const uint32_t* a, uint32_t b0, uint32_t b1){
    asm volatile("mma.sync.aligned.m16n8k16.row.col.f32.bf16.bf16.f32 "
        "{%0,%1,%2,%3}, {%4,%5,%6,%7}, {%8,%9}, {%0,%1,%2,%3};"
        : "+f"(c[0]), "+f"(c[1]), "+f"(c[2]), "+f"(c[3])
        : "r"(a[0]), "r"(a[1]), "r"(a[2]), "r"(a[3]), "r"(b0), "r"(b1));
}

// ---------- scratch ----------
__device__ float g_enc_out[BB*SS*EE];
__device__ float g_avg[BB*EE];
__device__ float g_ctx[BB*EE];
__device__ float g_h[BB*HH];
__device__ float g_c[BB*HH];
__device__ float g_gconst[BB*G4H];
__device__ float g_part[KSPLIT*BB*G4H];
__device__ float g_pre[MPAD*G4H];                    // per-step const gate input
__device__ __nv_bfloat16 g_Acat[(size_t)MPAD*KCAT];  // [Ah|Ah|Al] rows (zero beyond 3136)
__device__ __nv_bfloat16 g_Bcat[(size_t)VTS*KCAT];   // [Bh|Bl|Bh] rows

// ============================================================
// Encoder GEMM (fp32 FFMA2) — unchanged from round 1
// ============================================================
__global__ __launch_bounds__(256)
void enc_gemm(const int* __restrict__ src, const int* __restrict__ pos,
              const float* __restrict__ enc_emb, const float* __restrict__ pos_emb,
              const float* __restrict__ cat_W, const float* __restrict__ cat_b)
{
    __shared__ __align__(16) float As[128*20];
    __shared__ __align__(16) float Bs[16*132];
    const int m0 = blockIdx.x * 128;
    const int n0 = blockIdx.y * 128;
    const int tid = threadIdx.x;
    const int tx = tid & 15, ty = tid >> 4;

    ull acc[8][2][2];
    #pragma unroll
    for (int i=0;i<8;i++)
        #pragma unroll
        for (int q=0;q<2;q++){ acc[i][q][0]=0ull; acc[i][q][1]=0ull; }

    for (int kt = 0; kt < 1024; kt += 16){
        #pragma unroll
        for (int l=0;l<2;l++){
            int f4 = tid + 256*l;
            int row = f4 >> 2, k4 = (f4 & 3) << 2;
            int kg = kt + k4;
            int r = m0 + row;
            float4 v;
            if (kg < 512) v = *(const float4*)(enc_emb + (size_t)src[r]*512 + kg);
            else          v = *(const float4*)(pos_emb + (size_t)pos[r]*512 + (kg - 512));
            *(float4*)(As + row*20 + k4) = v;
        }
        #pragma unroll
        for (int l=0;l<2;l++){
            int f4 = tid + 256*l;
            int row = f4 >> 2, k4 = (f4 & 3) << 2;
            float4 v = *(const float4*)(cat_W + (size_t)(n0+row)*1024 + kt + k4);
            Bs[(k4+0)*132 + row] = v.x;
            Bs[(k4+1)*132 + row] = v.y;
            Bs[(k4+2)*132 + row] = v.z;
            Bs[(k4+3)*132 + row] = v.w;
        }
        __syncthreads();
        #pragma unroll
        for (int kq=0;kq<4;kq++){
            float4 av[8];
            #pragma unroll
            for (int i=0;i<8;i++) av[i] = *(const float4*)(As + (ty*8+i)*20 + kq*4);
            #pragma unroll
            for (int kk=0;kk<4;kk++){
                ull a2[8];
                #pragma unroll
                for (int i=0;i<8;i++){
                    float a = (kk==0)?av[i].x:(kk==1)?av[i].y:(kk==2)?av[i].z:av[i].w;
                    a2[i] = dup2(a);
                }
                const int k = kq*4+kk;
                #pragma unroll
                for (int q=0;q<2;q++){
                    ulonglong2 bv = *(const ulonglong2*)(Bs + k*132 + tx*4 + q*64);
                    #pragma unroll
                    for (int i=0;i<8;i++){ ffma2(acc[i][q][0], a2[i], bv.x);
                                           ffma2(acc[i][q][1], a2[i], bv.y); }
                }
            }
        }
        __syncthreads();
    }
    #pragma unroll
    for (int i=0;i<8;i++){
        int gm = m0 + ty*8 + i;
        #pragma unroll
        for (int q=0;q<2;q++){
            int gn = n0 + tx*4 + q*64;
            float2 p0 = unpk(acc[i][q][0]);
            float2 p1 = unpk(acc[i][q][1]);
            float4 bb = *(const float4*)(cat_b + gn);
            *(float4*)(g_enc_out + (size_t)gm*512 + gn) =
                make_float4(p0.x+bb.x, p0.y+bb.y, p1.x+bb.z, p1.y+bb.w);
        }
    }
}

__global__ void avg_kernel()
{
    int b = blockIdx.x, e = threadIdx.x;
    float s = 0.f;
    #pragma unroll 5
    for (int si=0; si<SS; si++) s += g_enc_out[(b*SS+si)*EE + e];
    g_avg[b*EE + e] = s * (1.0f/50.0f);
}

__global__ void h0_kernel(const float* __restrict__ scale_W, const float* __restrict__ scale_b)
{
    int gid = blockIdx.x*blockDim.x + threadIdx.x;
    int b = gid >> 10, h = gid & 1023;
    const float4* a = (const float4*)(g_avg + b*EE);
    const float4* w = (const float4*)(scale_W + (size_t)h*EE);
    float s = 0.f;
    #pragma unroll 8
    for (int i=0;i<128;i++){
        float4 av=a[i], wv=w[i];
        s += av.x*wv.x + av.y*wv.y + av.z*wv.z + av.w*wv.w;
    }
    float v = fmaxf(s + scale_b[h], 0.f);
    g_h[gid] = v; g_c[gid] = v;
}

__global__ void attn_kernel(const float* __restrict__ attn_W, const int* __restrict__ src)
{
    int b = blockIdx.x, tid = threadIdx.x;
    __shared__ float sc[56];
    __shared__ float aw[56];
    int w = tid >> 5, lane = tid & 31;
    for (int s = w; s < SS; s += 8){
        const float* row = g_enc_out + (size_t)(b*SS+s)*EE;
        float a = 0.f;
        for (int e = lane; e < EE; e += 32) a += row[e]*attn_W[e];
        #pragma unroll
        for (int o=16;o>0;o>>=1) a += __shfl_xor_sync(0xffffffffu, a, o);
        if (lane==0) sc[s] = a;
    }
    __syncthreads();
    if (tid == 0){
        float mx = -1e30f;
        for (int s=0;s<SS;s++) mx = fmaxf(mx, sc[s]);
        float tot = 0.f;
        for (int s=0;s<SS;s++){
            float e = (src[b*SS+s]==0) ? 0.f : expf(sc[s]-mx);
            aw[s] = e; tot += e;
        }
        float inv = 1.f/tot;
        for (int s=0;s<SS;s++) aw[s] *= inv;
    }
    __syncthreads();
    for (int e = tid; e < EE; e += blockDim.x){
        float a = 0.f;
        #pragma unroll 5
        for (int s=0;s<SS;s++) a += aw[s]*g_enc_out[(size_t)(b*SS+s)*EE + e];
        g_ctx[b*EE + e] = a;
    }
}

__global__ void gconst_kernel(const float* __restrict__ W_ih,
                              const float* __restrict__ b_ih, const float* __restrict__ b_hh)
{
    int gid = blockIdx.x*blockDim.x + threadIdx.x;
    int b = gid >> 12, j = gid & 4095;
    const float4* c4 = (const float4*)(g_ctx + b*EE);
    const float4* w4 = (const float4*)(W_ih + (size_t)j*1024 + 512);
    float s = 0.f;
    #pragma unroll 8
    for (int i=0;i<128;i++){
        float4 cv=c4[i], wv=w4[i];
        s += cv.x*wv.x + cv.y*wv.y + cv.z*wv.z + cv.w*wv.w;
    }
    g_gconst[gid] = s + b_ih[j] + b_hh[j];
}

// ============================================================
// Hoisted token-embedding GEMM for ALL steps:
// pre[r=t*64+b, j] = dec_emb[tok[b,t]] . W_ih[j,0:512] + gconst[b,j]
// M=3200, N=4096, K=512 (fp32 FFMA2)
// ============================================================
__global__ __launch_bounds__(256)
void dec_pre(const int* __restrict__ tgt, const float* __restrict__ dec_emb,
             const float* __restrict__ W_ih)
{
    __shared__ __align__(16) float As[128*20];
    __shared__ __align__(16) float Bs[16*132];
    const int m0 = blockIdx.x * 128;
    const int n0 = blockIdx.y * 128;
    const int tid = threadIdx.x;
    const int tx = tid & 15, ty = tid >> 4;

    ull acc[8][2][2];
    #pragma unroll
    for (int i=0;i<8;i++)
        #pragma unroll
        for (int q=0;q<2;q++){ acc[i][q][0]=0ull; acc[i][q][1]=0ull; }

    for (int kt = 0; kt < 512; kt += 16){
        #pragma unroll
        for (int l=0;l<2;l++){
            int f4 = tid + 256*l;
            int row = f4 >> 2, k4 = (f4 & 3) << 2;
            int r = m0 + row;
            int tok = tgt[(r & 63)*50 + (r >> 6)];
            float4 v = *(const float4*)(dec_emb + (size_t)tok*512 + kt + k4);
            *(float4*)(As + row*20 + k4) = v;
        }
        #pragma unroll
        for (int l=0;l<2;l++){
            int f4 = tid + 256*l;
            int row = f4 >> 2, k4 = (f4 & 3) << 2;
            float4 v = *(const float4*)(W_ih + (size_t)(n0+row)*1024 + kt + k4);
            Bs[(k4+0)*132 + row] = v.x;
            Bs[(k4+1)*132 + row] = v.y;
            Bs[(k4+2)*132 + row] = v.z;
            Bs[(k4+3)*132 + row] = v.w;
        }
        __syncthreads();
        #pragma unroll
        for (int kq=0;kq<4;kq++){
            float4 av[8];
            #pragma unroll
            for (int i=0;i<8;i++) av[i] = *(const float4*)(As + (ty*8+i)*20 + kq*4);
            #pragma unroll
            for (int kk=0;kk<4;kk++){
                ull a2[8];
                #pragma unroll
                for (int i=0;i<8;i++){
                    float a = (kk==0)?av[i].x:(kk==1)?av[i].y:(kk==2)?av[i].z:av[i].w;
                    a2[i] = dup2(a);
                }
                const int k = kq*4+kk;
                #pragma unroll
                for (int q=0;q<2;q++){
                    ulonglong2 bv = *(const ulonglong2*)(Bs + k*132 + tx*4 + q*64);
                    #pragma unroll
                    for (int i=0;i<8;i++){ ffma2(acc[i][q][0], a2[i], bv.x);
                                           ffma2(acc[i][q][1], a2[i], bv.y); }
                }
            }
        }
        __syncthreads();
    }
    #pragma unroll
    for (int i=0;i<8;i++){
        int gm = m0 + ty*8 + i;
        int b = gm & 63;
        #pragma unroll
        for (int q=0;q<2;q++){
            int gn = n0 + tx*4 + q*64;
            float2 p0 = unpk(acc[i][q][0]);
            float2 p1 = unpk(acc[i][q][1]);
            float4 gc = *(const float4*)(g_gconst + (size_t)b*G4H + gn);
            *(float4*)(g_pre + (size_t)gm*G4H + gn) =
                make_float4(p0.x+gc.x, p0.y+gc.y, p1.x+gc.z, p1.y+gc.w);
        }
    }
}

// ============================================================
// Per-step gates GEMM (split-K over K=1024): part = h . W_hh^T
// ============================================================
__global__ __launch_bounds__(128)
void gates_gemm(const float* __restrict__ W_hh)
{
    __shared__ __align__(16) float As[64*20];
    __shared__ __align__(16) float Bs[16*132];
    const int n0 = blockIdx.x * 128;
    const int kbase = blockIdx.y * KCHUNK;
    const int tid = threadIdx.x;
    const int tx = tid & 15, ty = tid >> 4;

    ull acc[8][2][2];
    #pragma unroll
    for (int i=0;i<8;i++)
        #pragma unroll
        for (int q=0;q<2;q++){ acc[i][q][0]=0ull; acc[i][q][1]=0ull; }

    for (int kt = 0; kt < KCHUNK; kt += 16){
        const int kg0 = kbase + kt;
        #pragma unroll
        for (int l=0;l<2;l++){
            int f4 = tid + 128*l;
            int row = f4 >> 2, k4 = (f4 & 3) << 2;
            float4 v = *(const float4*)(g_h + row*1024 + kg0 + k4);
            *(float4*)(As + row*20 + k4) = v;
        }
        #pragma unroll
        for (int l=0;l<4;l++){
            int f4 = tid + 128*l;
            int row = f4 >> 2, k4 = (f4 & 3) << 2;
            float4 v = *(const float4*)(W_hh + (size_t)(n0+row)*1024 + kg0 + k4);
            Bs[(k4+0)*132 + row] = v.x;
            Bs[(k4+1)*132 + row] = v.y;
            Bs[(k4+2)*132 + row] = v.z;
            Bs[(k4+3)*132 + row] = v.w;
        }
        __syncthreads();
        #pragma unroll
        for (int kq=0;kq<4;kq++){
            float4 av[8];
            #pragma unroll
            for (int i=0;i<8;i++) av[i] = *(const float4*)(As + (ty*8+i)*20 + kq*4);
            #pragma unroll
            for (int kk=0;kk<4;kk++){
                ull a2[8];
                #pragma unroll
                for (int i=0;i<8;i++){
                    float a = (kk==0)?av[i].x:(kk==1)?av[i].y:(kk==2)?av[i].z:av[i].w;
                    a2[i] = dup2(a);
                }
                const int k = kq*4+kk;
                #pragma unroll
                for (int q=0;q<2;q++){
                    ulonglong2 bv = *(const ulonglong2*)(Bs + k*132 + tx*4 + q*64);
                    #pragma unroll
                    for (int i=0;i<8;i++){ ffma2(acc[i][q][0], a2[i], bv.x);
                                           ffma2(acc[i][q][1], a2[i], bv.y); }
                }
            }
        }
        __syncthreads();
    }
    float* outp = g_part + (size_t)blockIdx.y*(BB*G4H);
    #pragma unroll
    for (int i=0;i<8;i++){
        int m = ty*8 + i;
        #pragma unroll
        for (int q=0;q<2;q++){
            int n = n0 + tx*4 + q*64;
            float2 p0 = unpk(acc[i][q][0]);
            float2 p1 = unpk(acc[i][q][1]);
            *(float4*)(outp + (size_t)m*G4H + n) = make_float4(p0.x, p0.y, p1.x, p1.y);
        }
    }
}

// ============================================================
// LSTM pointwise; emits h rows into A' = [Ah | Ah | Al]
// ============================================================
__global__ void lstm_pw(int t)
{
    int gid = blockIdx.x*blockDim.x + threadIdx.x;
    int b = gid >> 10, h = gid & 1023;
    size_t prow = (size_t)(t*64 + b)*G4H;
    float gi = g_pre[prow + h];
    float gf = g_pre[prow + 1024 + h];
    float gg = g_pre[prow + 2048 + h];
    float go = g_pre[prow + 3072 + h];
    int base = b*G4H;
    #pragma unroll
    for (int s=0;s<KSPLIT;s++){
        const float* p = g_part + (size_t)s*(BB*G4H) + base;
        gi += p[h]; gf += p[1024+h]; gg += p[2048+h]; go += p[3072+h];
    }
    float c  = g_c[gid];
    float ii = 1.f/(1.f+expf(-gi));
    float ff = 1.f/(1.f+expf(-gf));
    float oo = 1.f/(1.f+expf(-go));
    float gt = tanhf(gg);
    float cn = ff*c + ii*gt;
    float hn = oo*tanhf(cn);
    g_c[gid] = cn; g_h[gid] = hn;

    __nv_bfloat16 hhi = __float2bfloat16_rn(hn);
    float hif = __bfloat162float(hhi);
    __nv_bfloat16 hlo = __float2bfloat16_rn(hn - hif);
    size_t arow = (size_t)(t*64 + b)*KCAT;
    g_Acat[arow + h]        = hhi;
    g_Acat[arow + 1024 + h] = hhi;
    g_Acat[arow + 2048 + h] = hlo;
}

// ============================================================
// proj_W fp32 -> B' = [Bh | Bl | Bh] (bf16)
// ============================================================
__global__ __launch_bounds__(256)
void conv_w(const float* __restrict__ W)
{
    size_t i = (size_t)blockIdx.x*blockDim.x + threadIdx.x;   // 8,192,000 float4s
    int n = (int)(i >> 8);
    int k = (int)(i & 255) * 4;
    float4 v = ((const float4*)W)[i];
    __nv_bfloat16 h0 = __float2bfloat16_rn(v.x);
    __nv_bfloat16 h1 = __float2bfloat16_rn(v.y);
    __nv_bfloat16 h2 = __float2bfloat16_rn(v.z);
    __nv_bfloat16 h3 = __float2bfloat16_rn(v.w);
    __nv_bfloat16 l0 = __float2bfloat16_rn(v.x - __bfloat162float(h0));
    __nv_bfloat16 l1 = __float2bfloat16_rn(v.y - __bfloat162float(h1));
    __nv_bfloat16 l2 = __float2bfloat16_rn(v.z - __bfloat162float(h2));
    __nv_bfloat16 l3 = __float2bfloat16_rn(v.w - __bfloat162float(h3));
    ull hi, lo;
    asm("mov.b64 %0, {%1,%2,%3,%4};" : "=l"(hi)
        : "h"(*(unsigned short*)&h0), "h"(*(unsigned short*)&h1),
          "h"(*(unsigned short*)&h2), "h"(*(unsigned short*)&h3));
    asm("mov.b64 %0, {%1,%2,%3,%4};" : "=l"(lo)
        : "h"(*(unsigned short*)&l0), "h"(*(unsigned short*)&l1),
          "h"(*(unsigned short*)&l2), "h"(*(unsigned short*)&l3));
    size_t rb = (size_t)n*KCAT;
    *(ull*)(g_Bcat + rb + k)        = hi;
    *(ull*)(g_Bcat + rb + 1024 + k) = lo;
    *(ull*)(g_Bcat + rb + 2048 + k) = hi;
}

// ============================================================
// Projection via mma.sync bf16: out = A'(3200xK) . B'(32000xK)^T + bias
// CTA 128x128, 8 warps (4M x 2N), 3-stage cp.async pipeline, K=3072.
// smem rows padded to 80B -> conflict-free ldmatrix.
// ============================================================
#define NSTG 3
#define TSTAGE 10240            /* 128 rows * 80 B */
#define SM_PROJ (NSTG*2*TSTAGE) /* 61440 */

__global__ __launch_bounds__(256)
void proj_mma(float* __restrict__ out, const float* __restrict__ bias)
{
    extern __shared__ __align__(16) char sm[];
    const uint32_t uA = smem_u32(sm);
    const uint32_t uB = uA + NSTG*TSTAGE;
    const int tid = threadIdx.x;
    const int wid = tid >> 5, lane = tid & 31;
    const int m0 = blockIdx.x * 128;
    const int n0 = blockIdx.y * 128;
    const int wm = wid & 3, wn = wid >> 2;

    const int lrow = tid >> 2;            // 0..63
    const int lc   = (tid & 3);           // 16B chunk in 64B row

    float acc[2][8][4];
    #pragma unroll
    for (int a=0;a<2;a++)
        #pragma unroll
        for (int j=0;j<8;j++)
            #pragma unroll
            for (int x=0;x<4;x++) acc[a][j][x] = 0.f;

    const __nv_bfloat16* gA = g_Acat + (size_t)m0*KCAT;
    const __nv_bfloat16* gB = g_Bcat + (size_t)n0*KCAT;

    // ---- stage loader ----
    auto load_stage = [&](int slot, int ks){
        int k0 = ks * 32;
        #pragma unroll
        for (int half = 0; half < 2; half++){
            int row = lrow + half*64;
            cpasync16(uA + slot*TSTAGE + row*80 + lc*16,
                      gA + (size_t)row*KCAT + k0 + lc*8);
            cpasync16(uB + slot*TSTAGE + row*80 + lc*16,
                      gB + (size_t)row*KCAT + k0 + lc*8);
        }
        cp_commit();
    };

    load_stage(0, 0);
    load_stage(1, 1);

    const int g  = lane >> 3;     // ldmatrix tile group 0..3
    const int lr = lane & 7;

    for (int ks = 0; ks < 96; ks++){
        asm volatile("cp.async.wait_group 1;");
        __syncthreads();
        int ld = ks + NSTG - 1;
        if (ld < 96) load_stage(ld % NSTG, ld);
        else cp_commit();

        const uint32_t bufA = uA + (ks % NSTG)*TSTAGE;
        const uint32_t bufB = uB + (ks % NSTG)*TSTAGE;

        #pragma unroll
        for (int kk = 0; kk < 32; kk += 16){
            uint32_t afr[2][4];
            #pragma unroll
            for (int mi = 0; mi < 2; mi++){
                int row = wm*32 + mi*16 + ((g & 1) ? 8 : 0) + lr;
                int kof = kk + (g >> 1)*8;
                ldm4(afr[mi], bufA + row*80 + kof*2);
            }
            uint32_t bfr[4][4];
            #pragma unroll
            for (int p = 0; p < 4; p++){
                int row = wn*64 + p*16 + (g >> 1)*8 + lr;
                int kof = kk + (g & 1)*8;
                ldm4(bfr[p], bufB + row*80 + kof*2);
            }
            #pragma unroll
            for (int mi = 0; mi < 2; mi++)
                #pragma unroll
                for (int j = 0; j < 8; j++){
                    int p = j >> 1, h2 = (j & 1)*2;
                    mma16816(acc[mi][j], afr[mi], bfr[p][h2], bfr[p][h2+1]);
                }
        }
        __syncthreads();
    }

    // ---- epilogue ----
    const int tm = lane >> 2;
    const int tn = (lane & 3)*2;
    #pragma unroll
    for (int mi = 0; mi < 2; mi++){
        #pragma unroll
        for (int j = 0; j < 8; j++){
            int gn = n0 + wn*64 + j*8 + tn;
            float2 bb = *(const float2*)(bias + gn);
            int gm0 = m0 + wm*32 + mi*16 + tm;
            if (gm0 < MPROJ){
                float2 o; o.x = acc[mi][j][0] + bb.x; o.y = acc[mi][j][1] + bb.y;
                *(float2*)(out + (size_t)gm0*VTS + gn) = o;
            }
            int gm1 = gm0 + 8;
            if (gm1 < MPROJ){
                float2 o; o.x = acc[mi][j][2] + bb.x; o.y = acc[mi][j][3] + bb.y;
                *(float2*)(out + (size_t)gm1*VTS + gn) = o;
            }
        }
    }
}

// ============================================================
extern "C" void kernel_launch(void* const* d_in, const int* in_sizes, int n_in,
                              void* d_out, int out_size)
{
    const int*   src      = (const int*)  d_in[0];
    const int*   pos      = (const int*)  d_in[2];
    const int*   tgt      = (const int*)  d_in[3];
    const float* enc_emb  = (const float*)d_in[4];
    const float* pos_emb  = (const float*)d_in[5];
    const float* cat_W    = (const float*)d_in[6];
    const float* cat_b    = (const float*)d_in[7];
    const float* scale_W  = (const float*)d_in[8];
    const float* scale_b  = (const float*)d_in[9];
    const float* dec_emb  = (const float*)d_in[10];
    const float* attn_W   = (const float*)d_in[11];
    const float* W_ih     = (const float*)d_in[13];
    const float* W_hh     = (const float*)d_in[14];
    const float* b_ih     = (const float*)d_in[15];
    const float* b_hh     = (const float*)d_in[16];
    const float* proj_W   = (const float*)d_in[17];
    const float* proj_b   = (const float*)d_in[18];
    float* out = (float*)d_out;

    cudaFuncSetAttribute(proj_mma, cudaFuncAttributeMaxDynamicSharedMemorySize, SM_PROJ);

    // B' conversion (independent; overlaps encoder work in-order on stream)
    conv_w<<<32000, 256>>>(proj_W);

    // Encoder
    enc_gemm<<<dim3(25,4), 256>>>(src, pos, enc_emb, pos_emb, cat_W, cat_b);
    avg_kernel<<<64, 512>>>();
    h0_kernel<<<256, 256>>>(scale_W, scale_b);

    // Loop-invariant attention context + hoisted per-step constants
    attn_kernel<<<64, 256>>>(attn_W, src);
    gconst_kernel<<<1024, 256>>>(W_ih, b_ih, b_hh);
    dec_pre<<<dim3(25,32), 256>>>(tgt, dec_emb, W_ih);

    // Recurrence: only h . W_hh^T is sequential now (K=1024)
    for (int t = 0; t < NSTEP; t++){
        gates_gemm<<<dim3(32, KSPLIT), 128>>>(W_hh);
        lstm_pw<<<256, 256>>>(t);
    }

    // Tensor-core projection (single GEMM, K=3072 3-term concat)
    proj_mma<<<dim3(25,250), 256, SM_PROJ>>>(out, proj_b);
}

// round 7
// speedup vs baseline: 1.5428x; 1.5376x over previous
#include <cuda_runtime.h>
#include <cuda_bf16.h>
#include <cuda_fp16.h>
#include <math.h>
#include <stdint.h>

// Problem dims
#define BB 64
#define SS 50
#define EE 512
#define HH 1024
#define VTS 32000
#define NSTEP 49
#define MPROJ (NSTEP*BB)   /* 3136 */
#define MPAD  3200
#define G4H 4096
#define KSPLIT 8
#define KCHUNK 128         /* 1024/8 */
#define KA 1024            /* projection K (single fp16 term) */

typedef unsigned long long ull;

// ---------- packed f32x2 helpers ----------
__device__ __forceinline__ ull dup2(float x){
    ull r; asm("mov.b64 %0, {%1, %1};" : "=l"(r) : "f"(x)); return r;
}
__device__ __forceinline__ void ffma2(ull &d, ull a, ull b){
    asm("fma.rn.f32x2 %0, %1, %2, %0;" : "+l"(d) : "l"(a), "l"(b));
}
__device__ __forceinline__ float2 unpk(ull v){
    float2 f; asm("mov.b64 {%0, %1}, %2;" : "=f"(f.x), "=f"(f.y) : "l"(v)); return f;
}

// ---------- baseline-PTX tensor helpers ----------
__device__ __forceinline__ uint32_t smem_u32(const void* p){
    uint32_t a;
    asm("{ .reg .u64 t; cvta.to.shared.u64 t, %1; cvt.u32.u64 %0, t; }" : "=r"(a) : "l"(p));
    return a;
}
__device__ __forceinline__ void cpasync16(uint32_t dst, const void* src){
    asm volatile("cp.async.cg.shared.global [%0], [%1], 16;" :: "r"(dst), "l"(src));
}
__device__ __forceinline__ void cp_commit(){
    asm volatile("cp.async.commit_group;");
}
__device__ __forceinline__ void ldm4(uint32_t* r, uint32_t a){
    asm volatile("ldmatrix.sync.aligned.m8n8.x4.shared.b16 {%0,%1,%2,%3}, [%4];"
        : "=r"(r[0]), "=r"(r[1]), "=r"(r[2]), "=r"(r[3]) : "r"(a));
}
__device__ __forceinline__ void mma16816h(float* c, const uint32_t* a, uint32_t b0, uint32_t b1){
    asm volatile("mma.sync.aligned.m16n8k16.row.col.f32.f16.f16.f32 "
        "{%0,%1,%2,%3}, {%4,%5,%6,%7}, {%8,%9}, {%0,%1,%2,%3};"
        : "+f"(c[0]), "+f"(c[1]), "+f"(c[2]), "+f"(c[3])
        : "r"(a[0]), "r"(a[1]), "r"(a[2]), "r"(a[3]), "r"(b0), "r"(b1));
}

// ---------- scratch ----------
__device__ float g_enc_out[BB*SS*EE];
__device__ float g_avg[BB*EE];
__device__ float g_ctx[BB*EE];
__device__ float g_h[BB*HH];
__device__ float g_c[BB*HH];
__device__ float g_gconst[BB*G4H];
__device__ float g_part[KSPLIT*BB*G4H];
__device__ float g_pre[MPAD*G4H];                // per-step const gate input
__device__ __half g_Ah[(size_t)MPAD*KA];         // fp16 hidden states (rows >=3136 stay zero)
__device__ __half g_Bh[(size_t)VTS*KA];          // fp16 proj weights

// ============================================================
// Encoder GEMM (fp32 FFMA2)
// ============================================================
__global__ __launch_bounds__(256)
void enc_gemm(const int* __restrict__ src, const int* __restrict__ pos,
              const float* __restrict__ enc_emb, const float* __restrict__ pos_emb,
              const float* __restrict__ cat_W, const float* __restrict__ cat_b)
{
    __shared__ __align__(16) float As[128*20];
    __shared__ __align__(16) float Bs[16*132];
    const int m0 = blockIdx.x * 128;
    const int n0 = blockIdx.y * 128;
    const int tid = threadIdx.x;
    const int tx = tid & 15, ty = tid >> 4;

    ull acc[8][2][2];
    #pragma unroll
    for (int i=0;i<8;i++)
        #pragma unroll
        for (int q=0;q<2;q++){ acc[i][q][0]=0ull; acc[i][q][1]=0ull; }

    for (int kt = 0; kt < 1024; kt += 16){
        #pragma unroll
        for (int l=0;l<2;l++){
            int f4 = tid + 256*l;
            int row = f4 >> 2, k4 = (f4 & 3) << 2;
            int kg = kt + k4;
            int r = m0 + row;
            float4 v;
            if (kg < 512) v = *(const float4*)(enc_emb + (size_t)src[r]*512 + kg);
            else          v = *(const float4*)(pos_emb + (size_t)pos[r]*512 + (kg - 512));
            *(float4*)(As + row*20 + k4) = v;
        }
        #pragma unroll
        for (int l=0;l<2;l++){
            int f4 = tid + 256*l;
            int row = f4 >> 2, k4 = (f4 & 3) << 2;
            float4 v = *(const float4*)(cat_W + (size_t)(n0+row)*1024 + kt + k4);
            Bs[(k4+0)*132 + row] = v.x;
            Bs[(k4+1)*132 + row] = v.y;
            Bs[(k4+2)*132 + row] = v.z;
            Bs[(k4+3)*132 + row] = v.w;
        }
        __syncthreads();
        #pragma unroll
        for (int kq=0;kq<4;kq++){
            float4 av[8];
            #pragma unroll
            for (int i=0;i<8;i++) av[i] = *(const float4*)(As + (ty*8+i)*20 + kq*4);
            #pragma unroll
            for (int kk=0;kk<4;kk++){
                ull a2[8];
                #pragma unroll
                for (int i=0;i<8;i++){
                    float a = (kk==0)?av[i].x:(kk==1)?av[i].y:(kk==2)?av[i].z:av[i].w;
                    a2[i] = dup2(a);
                }
                const int k = kq*4+kk;
                #pragma unroll
                for (int q=0;q<2;q++){
                    ulonglong2 bv = *(const ulonglong2*)(Bs + k*132 + tx*4 + q*64);
                    #pragma unroll
                    for (int i=0;i<8;i++){ ffma2(acc[i][q][0], a2[i], bv.x);
                                           ffma2(acc[i][q][1], a2[i], bv.y); }
                }
            }
        }
        __syncthreads();
    }
    #pragma unroll
    for (int i=0;i<8;i++){
        int gm = m0 + ty*8 + i;
        #pragma unroll
        for (int q=0;q<2;q++){
            int gn = n0 + tx*4 + q*64;
            float2 p0 = unpk(acc[i][q][0]);
            float2 p1 = unpk(acc[i][q][1]);
            float4 bb = *(const float4*)(cat_b + gn);
            *(float4*)(g_enc_out + (size_t)gm*512 + gn) =
                make_float4(p0.x+bb.x, p0.y+bb.y, p1.x+bb.z, p1.y+bb.w);
        }
    }
}

__global__ void avg_kernel()
{
    int b = blockIdx.x, e = threadIdx.x;
    float s = 0.f;
    #pragma unroll 5
    for (int si=0; si<SS; si++) s += g_enc_out[(b*SS+si)*EE + e];
    g_avg[b*EE + e] = s * (1.0f/50.0f);
}

__global__ void h0_kernel(const float* __restrict__ scale_W, const float* __restrict__ scale_b)
{
    int gid = blockIdx.x*blockDim.x + threadIdx.x;
    int b = gid >> 10, h = gid & 1023;
    const float4* a = (const float4*)(g_avg + b*EE);
    const float4* w = (const float4*)(scale_W + (size_t)h*EE);
    float s = 0.f;
    #pragma unroll 8
    for (int i=0;i<128;i++){
        float4 av=a[i], wv=w[i];
        s += av.x*wv.x + av.y*wv.y + av.z*wv.z + av.w*wv.w;
    }
    float v = fmaxf(s + scale_b[h], 0.f);
    g_h[gid] = v; g_c[gid] = v;
}

__global__ void attn_kernel(const float* __restrict__ attn_W, const int* __restrict__ src)
{
    int b = blockIdx.x, tid = threadIdx.x;
    __shared__ float sc[56];
    __shared__ float aw[56];
    int w = tid >> 5, lane = tid & 31;
    for (int s = w; s < SS; s += 8){
        const float* row = g_enc_out + (size_t)(b*SS+s)*EE;
        float a = 0.f;
        for (int e = lane; e < EE; e += 32) a += row[e]*attn_W[e];
        #pragma unroll
        for (int o=16;o>0;o>>=1) a += __shfl_xor_sync(0xffffffffu, a, o);
        if (lane==0) sc[s] = a;
    }
    __syncthreads();
    if (tid == 0){
        float mx = -1e30f;
        for (int s=0;s<SS;s++) mx = fmaxf(mx, sc[s]);
        float tot = 0.f;
        for (int s=0;s<SS;s++){
            float e = (src[b*SS+s]==0) ? 0.f : expf(sc[s]-mx);
            aw[s] = e; tot += e;
        }
        float inv = 1.f/tot;
        for (int s=0;s<SS;s++) aw[s] *= inv;
    }
    __syncthreads();
    for (int e = tid; e < EE; e += blockDim.x){
        float a = 0.f;
        #pragma unroll 5
        for (int s=0;s<SS;s++) a += aw[s]*g_enc_out[(size_t)(b*SS+s)*EE + e];
        g_ctx[b*EE + e] = a;
    }
}

__global__ void gconst_kernel(const float* __restrict__ W_ih,
                              const float* __restrict__ b_ih, const float* __restrict__ b_hh)
{
    int gid = blockIdx.x*blockDim.x + threadIdx.x;
    int b = gid >> 12, j = gid & 4095;
    const float4* c4 = (const float4*)(g_ctx + b*EE);
    const float4* w4 = (const float4*)(W_ih + (size_t)j*1024 + 512);
    float s = 0.f;
    #pragma unroll 8
    for (int i=0;i<128;i++){
        float4 cv=c4[i], wv=w4[i];
        s += cv.x*wv.x + cv.y*wv.y + cv.z*wv.z + cv.w*wv.w;
    }
    g_gconst[gid] = s + b_ih[j] + b_hh[j];
}

// ============================================================
// Hoisted token-embedding GEMM for ALL steps (fp32)
// ============================================================
__global__ __launch_bounds__(256)
void dec_pre(const int* __restrict__ tgt, const float* __restrict__ dec_emb,
             const float* __restrict__ W_ih)
{
    __shared__ __align__(16) float As[128*20];
    __shared__ __align__(16) float Bs[16*132];
    const int m0 = blockIdx.x * 128;
    const int n0 = blockIdx.y * 128;
    const int tid = threadIdx.x;
    const int tx = tid & 15, ty = tid >> 4;

    ull acc[8][2][2];
    #pragma unroll
    for (int i=0;i<8;i++)
        #pragma unroll
        for (int q=0;q<2;q++){ acc[i][q][0]=0ull; acc[i][q][1]=0ull; }

    for (int kt = 0; kt < 512; kt += 16){
        #pragma unroll
        for (int l=0;l<2;l++){
            int f4 = tid + 256*l;
            int row = f4 >> 2, k4 = (f4 & 3) << 2;
            int r = m0 + row;
            int tok = tgt[(r & 63)*50 + (r >> 6)];
            float4 v = *(const float4*)(dec_emb + (size_t)tok*512 + kt + k4);
            *(float4*)(As + row*20 + k4) = v;
        }
        #pragma unroll
        for (int l=0;l<2;l++){
            int f4 = tid + 256*l;
            int row = f4 >> 2, k4 = (f4 & 3) << 2;
            float4 v = *(const float4*)(W_ih + (size_t)(n0+row)*1024 + kt + k4);
            Bs[(k4+0)*132 + row] = v.x;
            Bs[(k4+1)*132 + row] = v.y;
            Bs[(k4+2)*132 + row] = v.z;
            Bs[(k4+3)*132 + row] = v.w;
        }
        __syncthreads();
        #pragma unroll
        for (int kq=0;kq<4;kq++){
            float4 av[8];
            #pragma unroll
            for (int i=0;i<8;i++) av[i] = *(const float4*)(As + (ty*8+i)*20 + kq*4);
            #pragma unroll
            for (int kk=0;kk<4;kk++){
                ull a2[8];
                #pragma unroll
                for (int i=0;i<8;i++){
                    float a = (kk==0)?av[i].x:(kk==1)?av[i].y:(kk==2)?av[i].z:av[i].w;
                    a2[i] = dup2(a);
                }
                const int k = kq*4+kk;
                #pragma unroll
                for (int q=0;q<2;q++){
                    ulonglong2 bv = *(const ulonglong2*)(Bs + k*132 + tx*4 + q*64);
                    #pragma unroll
                    for (int i=0;i<8;i++){ ffma2(acc[i][q][0], a2[i], bv.x);
                                           ffma2(acc[i][q][1], a2[i], bv.y); }
                }
            }
        }
        __syncthreads();
    }
    #pragma unroll
    for (int i=0;i<8;i++){
        int gm = m0 + ty*8 + i;
        int b = gm & 63;
        #pragma unroll
        for (int q=0;q<2;q++){
            int gn = n0 + tx*4 + q*64;
            float2 p0 = unpk(acc[i][q][0]);
            float2 p1 = unpk(acc[i][q][1]);
            float4 gc = *(const float4*)(g_gconst + (size_t)b*G4H + gn);
            *(float4*)(g_pre + (size_t)gm*G4H + gn) =
                make_float4(p0.x+gc.x, p0.y+gc.y, p1.x+gc.z, p1.y+gc.w);
        }
    }
}

// ============================================================
// Per-step gates GEMM (split-K over K=1024): part = h . W_hh^T
// ============================================================
__global__ __launch_bounds__(128)
void gates_gemm(const float* __restrict__ W_hh)
{
    __shared__ __align__(16) float As[64*20];
    __shared__ __align__(16) float Bs[16*132];
    const int n0 = blockIdx.x * 128;
    const int kbase = blockIdx.y * KCHUNK;
    const int tid = threadIdx.x;
    const int tx = tid & 15, ty = tid >> 4;

    ull acc[8][2][2];
    #pragma unroll
    for (int i=0;i<8;i++)
        #pragma unroll
        for (int q=0;q<2;q++){ acc[i][q][0]=0ull; acc[i][q][1]=0ull; }

    for (int kt = 0; kt < KCHUNK; kt += 16){
        const int kg0 = kbase + kt;
        #pragma unroll
        for (int l=0;l<2;l++){
            int f4 = tid + 128*l;
            int row = f4 >> 2, k4 = (f4 & 3) << 2;
            float4 v = *(const float4*)(g_h + row*1024 + kg0 + k4);
            *(float4*)(As + row*20 + k4) = v;
        }
        #pragma unroll
        for (int l=0;l<4;l++){
            int f4 = tid + 128*l;
            int row = f4 >> 2, k4 = (f4 & 3) << 2;
            float4 v = *(const float4*)(W_hh + (size_t)(n0+row)*1024 + kg0 + k4);
            Bs[(k4+0)*132 + row] = v.x;
            Bs[(k4+1)*132 + row] = v.y;
            Bs[(k4+2)*132 + row] = v.z;
            Bs[(k4+3)*132 + row] = v.w;
        }
        __syncthreads();
        #pragma unroll
        for (int kq=0;kq<4;kq++){
            float4 av[8];
            #pragma unroll
            for (int i=0;i<8;i++) av[i] = *(const float4*)(As + (ty*8+i)*20 + kq*4);
            #pragma unroll
            for (int kk=0;kk<4;kk++){
                ull a2[8];
                #pragma unroll
                for (int i=0;i<8;i++){
                    float a = (kk==0)?av[i].x:(kk==1)?av[i].y:(kk==2)?av[i].z:av[i].w;
                    a2[i] = dup2(a);
                }
                const int k = kq*4+kk;
                #pragma unroll
                for (int q=0;q<2;q++){
                    ulonglong2 bv = *(const ulonglong2*)(Bs + k*132 + tx*4 + q*64);
                    #pragma unroll
                    for (int i=0;i<8;i++){ ffma2(acc[i][q][0], a2[i], bv.x);
                                           ffma2(acc[i][q][1], a2[i], bv.y); }
                }
            }
        }
        __syncthreads();
    }
    float* outp = g_part + (size_t)blockIdx.y*(BB*G4H);
    #pragma unroll
    for (int i=0;i<8;i++){
        int m = ty*8 + i;
        #pragma unroll
        for (int q=0;q<2;q++){
            int n = n0 + tx*4 + q*64;
            float2 p0 = unpk(acc[i][q][0]);
            float2 p1 = unpk(acc[i][q][1]);
            *(float4*)(outp + (size_t)m*G4H + n) = make_float4(p0.x, p0.y, p1.x, p1.y);
        }
    }
}

// ============================================================
// LSTM pointwise; emits h row as fp16 for the projection
// ============================================================
__global__ void lstm_pw(int t)
{
    int gid = blockIdx.x*blockDim.x + threadIdx.x;
    int b = gid >> 10, h = gid & 1023;
    size_t prow = (size_t)(t*64 + b)*G4H;
    float gi = g_pre[prow + h];
    float gf = g_pre[prow + 1024 + h];
    float gg = g_pre[prow + 2048 + h];
    float go = g_pre[prow + 3072 + h];
    int base = b*G4H;
    #pragma unroll
    for (int s=0;s<KSPLIT;s++){
        const float* p = g_part + (size_t)s*(BB*G4H) + base;
        gi += p[h]; gf += p[1024+h]; gg += p[2048+h]; go += p[3072+h];
    }
    float c  = g_c[gid];
    float ii = 1.f/(1.f+expf(-gi));
    float ff = 1.f/(1.f+expf(-gf));
    float oo = 1.f/(1.f+expf(-go));
    float gt = tanhf(gg);
    float cn = ff*c + ii*gt;
    float hn = oo*tanhf(cn);
    g_c[gid] = cn; g_h[gid] = hn;

    g_Ah[(size_t)(t*64 + b)*KA + h] = __float2half_rn(hn);
}

// ============================================================
// proj_W fp32 -> fp16
// ============================================================
__global__ __launch_bounds__(256)
void conv_w(const float* __restrict__ W)
{
    size_t i = (size_t)blockIdx.x*blockDim.x + threadIdx.x;   // 8,192,000 float4s
    float4 v = ((const float4*)W)[i];
    __half h0 = __float2half_rn(v.x);
    __half h1 = __float2half_rn(v.y);
    __half h2 = __float2half_rn(v.z);
    __half h3 = __float2half_rn(v.w);
    ull packed;
    asm("mov.b64 %0, {%1,%2,%3,%4};" : "=l"(packed)
        : "h"(*(unsigned short*)&h0), "h"(*(unsigned short*)&h1),
          "h"(*(unsigned short*)&h2), "h"(*(unsigned short*)&h3));
    *(ull*)(g_Bh + i*4) = packed;
}

// ============================================================
// Projection via mma.sync fp16: out = A(3200x1024) . B(32000x1024)^T + bias
// CTA 128x128, 8 warps (4M x 2N), 3-stage cp.async pipeline.
// smem rows padded to 80B -> conflict-free ldmatrix.
// ============================================================
#define NSTG 3
#define TSTAGE 10240            /* 128 rows * 80 B */
#define SM_PROJ (NSTG*2*TSTAGE) /* 61440 */
#define NKS (KA/32)             /* 32 k-chunks */

__global__ __launch_bounds__(256)
void proj_mma(float* __restrict__ out, const float* __restrict__ bias)
{
    extern __shared__ __align__(16) char sm[];
    const uint32_t uA = smem_u32(sm);
    const uint32_t uB = uA + NSTG*TSTAGE;
    const int tid = threadIdx.x;
    const int wid = tid >> 5, lane = tid & 31;
    const int m0 = blockIdx.x * 128;
    const int n0 = blockIdx.y * 128;
    const int wm = wid & 3, wn = wid >> 2;

    const int lrow = tid >> 2;            // 0..63
    const int lc   = (tid & 3);           // 16B chunk in 64B row

    float acc[2][8][4];
    #pragma unroll
    for (int a=0;a<2;a++)
        #pragma unroll
        for (int j=0;j<8;j++)
            #pragma unroll
            for (int x=0;x<4;x++) acc[a][j][x] = 0.f;

    const __half* gA = g_Ah + (size_t)m0*KA;
    const __half* gB = g_Bh + (size_t)n0*KA;

    auto load_stage = [&](int slot, int ks){
        int k0 = ks * 32;
        #pragma unroll
        for (int half_ = 0; half_ < 2; half_++){
            int row = lrow + half_*64;
            cpasync16(uA + slot*TSTAGE + row*80 + lc*16,
                      gA + (size_t)row*KA + k0 + lc*8);
            cpasync16(uB + slot*TSTAGE + row*80 + lc*16,
                      gB + (size_t)row*KA + k0 + lc*8);
        }
        cp_commit();
    };

    load_stage(0, 0);
    load_stage(1, 1);

    const int g  = lane >> 3;     // ldmatrix tile group 0..3
    const int lr = lane & 7;

    for (int ks = 0; ks < NKS; ks++){
        asm volatile("cp.async.wait_group 1;");
        __syncthreads();
        int ld = ks + NSTG - 1;
        if (ld < NKS) load_stage(ld % NSTG, ld);
        else cp_commit();

        const uint32_t bufA = uA + (ks % NSTG)*TSTAGE;
        const uint32_t bufB = uB + (ks % NSTG)*TSTAGE;

        #pragma unroll
        for (int kk = 0; kk < 32; kk += 16){
            uint32_t afr[2][4];
            #pragma unroll
            for (int mi = 0; mi < 2; mi++){
                int row = wm*32 + mi*16 + ((g & 1) ? 8 : 0) + lr;
                int kof = kk + (g >> 1)*8;
                ldm4(afr[mi], bufA + row*80 + kof*2);
            }
            uint32_t bfr[4][4];
            #pragma unroll
            for (int p = 0; p < 4; p++){
                int row = wn*64 + p*16 + (g >> 1)*8 + lr;
                int kof = kk + (g & 1)*8;
                ldm4(bfr[p], bufB + row*80 + kof*2);
            }
            #pragma unroll
            for (int mi = 0; mi < 2; mi++)
                #pragma unroll
                for (int j = 0; j < 8; j++){
                    int p = j >> 1, h2 = (j & 1)*2;
                    mma16816h(acc[mi][j], afr[mi], bfr[p][h2], bfr[p][h2+1]);
                }
        }
        __syncthreads();
    }

    // ---- epilogue ----
    const int tm = lane >> 2;
    const int tn = (lane & 3)*2;
    #pragma unroll
    for (int mi = 0; mi < 2; mi++){
        #pragma unroll
        for (int j = 0; j < 8; j++){
            int gn = n0 + wn*64 + j*8 + tn;
            float2 bb = *(const float2*)(bias + gn);
            int gm0 = m0 + wm*32 + mi*16 + tm;
            if (gm0 < MPROJ){
                float2 o; o.x = acc[mi][j][0] + bb.x; o.y = acc[mi][j][1] + bb.y;
                *(float2*)(out + (size_t)gm0*VTS + gn) = o;
            }
            int gm1 = gm0 + 8;
            if (gm1 < MPROJ){
                float2 o; o.x = acc[mi][j][2] + bb.x; o.y = acc[mi][j][3] + bb.y;
                *(float2*)(out + (size_t)gm1*VTS + gn) = o;
            }
        }
    }
}

// ============================================================
extern "C" void kernel_launch(void* const* d_in, const int* in_sizes, int n_in,
                              void* d_out, int out_size)
{
    const int*   src      = (const int*)  d_in[0];
    const int*   pos      = (const int*)  d_in[2];
    const int*   tgt      = (const int*)  d_in[3];
    const float* enc_emb  = (const float*)d_in[4];
    const float* pos_emb  = (const float*)d_in[5];
    const float* cat_W    = (const float*)d_in[6];
    const float* cat_b    = (const float*)d_in[7];
    const float* scale_W  = (const float*)d_in[8];
    const float* scale_b  = (const float*)d_in[9];
    const float* dec_emb  = (const float*)d_in[10];
    const float* attn_W   = (const float*)d_in[11];
    const float* W_ih     = (const float*)d_in[13];
    const float* W_hh     = (const float*)d_in[14];
    const float* b_ih     = (const float*)d_in[15];
    const float* b_hh     = (const float*)d_in[16];
    const float* proj_W   = (const float*)d_in[17];
    const float* proj_b   = (const float*)d_in[18];
    float* out = (float*)d_out;

    cudaFuncSetAttribute(proj_mma, cudaFuncAttributeMaxDynamicSharedMemorySize, SM_PROJ);

    // B conversion (independent; overlaps nothing but is cheap now)
    conv_w<<<32000, 256>>>(proj_W);

    // Encoder
    enc_gemm<<<dim3(25,4), 256>>>(src, pos, enc_emb, pos_emb, cat_W, cat_b);
    avg_kernel<<<64, 512>>>();
    h0_kernel<<<256, 256>>>(scale_W, scale_b);

    // Loop-invariant attention context + hoisted per-step constants
    attn_kernel<<<64, 256>>>(attn_W, src);
    gconst_kernel<<<1024, 256>>>(W_ih, b_ih, b_hh);
    dec_pre<<<dim3(25,32), 256>>>(tgt, dec_emb, W_ih);

    // Recurrence: only h . W_hh^T is sequential (K=1024, fp32)
    for (int t = 0; t < NSTEP; t++){
        gates_gemm<<<dim3(32, KSPLIT), 128>>>(W_hh);
        lstm_pw<<<256, 256>>>(t);
    }

    // Single fp16 tensor-core projection (K=1024)
    proj_mma<<<dim3(25,250), 256, SM_PROJ>>>(out, proj_b);
}

// round 8
// speedup vs baseline: 1.6095x; 1.0432x over previous
#include <cuda_runtime.h>
#include <cuda_bf16.h>
#include <cuda_fp16.h>
#include <math.h>
#include <stdint.h>

// Problem dims
#define BB 64
#define SS 50
#define EE 512
#define HH 1024
#define VTS 32000
#define NSTEP 49
#define MPROJ (NSTEP*BB)   /* 3136 */
#define MPAD  3200
#define G4H 4096
#define KSPLIT 8
#define KCHUNK 128         /* 1024/8 */
#define KA 1024            /* projection K */
#define DCTA 256           /* persistent decoder grid */

typedef unsigned long long ull;

// ---------- packed f32x2 helpers ----------
__device__ __forceinline__ ull dup2(float x){
    ull r; asm("mov.b64 %0, {%1, %1};" : "=l"(r) : "f"(x)); return r;
}
__device__ __forceinline__ void ffma2(ull &d, ull a, ull b){
    asm("fma.rn.f32x2 %0, %1, %2, %0;" : "+l"(d) : "l"(a), "l"(b));
}
__device__ __forceinline__ float2 unpk(ull v){
    float2 f; asm("mov.b64 {%0, %1}, %2;" : "=f"(f.x), "=f"(f.y) : "l"(v)); return f;
}

// ---------- baseline-PTX tensor helpers ----------
__device__ __forceinline__ uint32_t smem_u32(const void* p){
    uint32_t a;
    asm("{ .reg .u64 t; cvta.to.shared.u64 t, %1; cvt.u32.u64 %0, t; }" : "=r"(a) : "l"(p));
    return a;
}
__device__ __forceinline__ void cpasync16(uint32_t dst, const void* src){
    asm volatile("cp.async.cg.shared.global [%0], [%1], 16;" :: "r"(dst), "l"(src));
}
__device__ __forceinline__ void cp_commit(){
    asm volatile("cp.async.commit_group;");
}
__device__ __forceinline__ void ldm4(uint32_t* r, uint32_t a){
    asm volatile("ldmatrix.sync.aligned.m8n8.x4.shared.b16 {%0,%1,%2,%3}, [%4];"
        : "=r"(r[0]), "=r"(r[1]), "=r"(r[2]), "=r"(r[3]) : "r"(a));
}
__device__ __forceinline__ void mma16816h(float* c, const uint32_t* a, uint32_t b0, uint32_t b1){
    asm volatile("mma.sync.aligned.m16n8k16.row.col.f32.f16.f16.f32 "
        "{%0,%1,%2,%3}, {%4,%5,%6,%7}, {%8,%9}, {%0,%1,%2,%3};"
        : "+f"(c[0]), "+f"(c[1]), "+f"(c[2]), "+f"(c[3])
        : "r"(a[0]), "r"(a[1]), "r"(a[2]), "r"(a[3]), "r"(b0), "r"(b1));
}

// ---------- scratch ----------
__device__ float g_enc_out[BB*SS*EE];
__device__ float g_avg[BB*EE];
__device__ float g_ctx[BB*EE];
__device__ float g_h[BB*HH];
__device__ float g_c[BB*HH];
__device__ float g_gconst[BB*G4H];
__device__ float g_part[KSPLIT*BB*G4H];
__device__ float g_pre[MPAD*G4H];
__device__ __half g_Ah[(size_t)MPAD*KA];
__device__ __half g_Bh[(size_t)VTS*KA];

// ---------- grid barrier state ----------
__device__ unsigned g_bcount;
__device__ volatile unsigned g_bepoch;

__device__ __forceinline__ void gbar(unsigned &target){
    target += 1u;
    __syncthreads();
    if (threadIdx.x == 0){
        __threadfence();
        unsigned a = atomicAdd(&g_bcount, 1u);
        if (a == DCTA-1u){
            g_bcount = 0u;               // safe: re-arrivals only after epoch bump
            __threadfence();
            g_bepoch = g_bepoch + 1u;    // single writer
        } else {
            while ((int)(g_bepoch - target) < 0) __nanosleep(64);
        }
    }
    __syncthreads();
}

// ============================================================
// Encoder GEMM (fp32 FFMA2)
// ============================================================
__global__ __launch_bounds__(256)
void enc_gemm(const int* __restrict__ src, const int* __restrict__ pos,
              const float* __restrict__ enc_emb, const float* __restrict__ pos_emb,
              const float* __restrict__ cat_W, const float* __restrict__ cat_b)
{
    __shared__ __align__(16) float As[128*20];
    __shared__ __align__(16) float Bs[16*132];
    const int m0 = blockIdx.x * 128;
    const int n0 = blockIdx.y * 128;
    const int tid = threadIdx.x;
    const int tx = tid & 15, ty = tid >> 4;

    ull acc[8][2][2];
    #pragma unroll
    for (int i=0;i<8;i++)
        #pragma unroll
        for (int q=0;q<2;q++){ acc[i][q][0]=0ull; acc[i][q][1]=0ull; }

    for (int kt = 0; kt < 1024; kt += 16){
        #pragma unroll
        for (int l=0;l<2;l++){
            int f4 = tid + 256*l;
            int row = f4 >> 2, k4 = (f4 & 3) << 2;
            int kg = kt + k4;
            int r = m0 + row;
            float4 v;
            if (kg < 512) v = *(const float4*)(enc_emb + (size_t)src[r]*512 + kg);
            else          v = *(const float4*)(pos_emb + (size_t)pos[r]*512 + (kg - 512));
            *(float4*)(As + row*20 + k4) = v;
        }
        #pragma unroll
        for (int l=0;l<2;l++){
            int f4 = tid + 256*l;
            int row = f4 >> 2, k4 = (f4 & 3) << 2;
            float4 v = *(const float4*)(cat_W + (size_t)(n0+row)*1024 + kt + k4);
            Bs[(k4+0)*132 + row] = v.x;
            Bs[(k4+1)*132 + row] = v.y;
            Bs[(k4+2)*132 + row] = v.z;
            Bs[(k4+3)*132 + row] = v.w;
        }
        __syncthreads();
        #pragma unroll
        for (int kq=0;kq<4;kq++){
            float4 av[8];
            #pragma unroll
            for (int i=0;i<8;i++) av[i] = *(const float4*)(As + (ty*8+i)*20 + kq*4);
            #pragma unroll
            for (int kk=0;kk<4;kk++){
                ull a2[8];
                #pragma unroll
                for (int i=0;i<8;i++){
                    float a = (kk==0)?av[i].x:(kk==1)?av[i].y:(kk==2)?av[i].z:av[i].w;
                    a2[i] = dup2(a);
                }
                const int k = kq*4+kk;
                #pragma unroll
                for (int q=0;q<2;q++){
                    ulonglong2 bv = *(const ulonglong2*)(Bs + k*132 + tx*4 + q*64);
                    #pragma unroll
                    for (int i=0;i<8;i++){ ffma2(acc[i][q][0], a2[i], bv.x);
                                           ffma2(acc[i][q][1], a2[i], bv.y); }
                }
            }
        }
        __syncthreads();
    }
    #pragma unroll
    for (int i=0;i<8;i++){
        int gm = m0 + ty*8 + i;
        #pragma unroll
        for (int q=0;q<2;q++){
            int gn = n0 + tx*4 + q*64;
            float2 p0 = unpk(acc[i][q][0]);
            float2 p1 = unpk(acc[i][q][1]);
            float4 bb = *(const float4*)(cat_b + gn);
            *(float4*)(g_enc_out + (size_t)gm*512 + gn) =
                make_float4(p0.x+bb.x, p0.y+bb.y, p1.x+bb.z, p1.y+bb.w);
        }
    }
}

__global__ void avg_kernel()
{
    int b = blockIdx.x, e = threadIdx.x;
    float s = 0.f;
    #pragma unroll 5
    for (int si=0; si<SS; si++) s += g_enc_out[(b*SS+si)*EE + e];
    g_avg[b*EE + e] = s * (1.0f/50.0f);
}

__global__ void h0_kernel(const float* __restrict__ scale_W, const float* __restrict__ scale_b)
{
    int gid = blockIdx.x*blockDim.x + threadIdx.x;
    int b = gid >> 10, h = gid & 1023;
    const float4* a = (const float4*)(g_avg + b*EE);
    const float4* w = (const float4*)(scale_W + (size_t)h*EE);
    float s = 0.f;
    #pragma unroll 8
    for (int i=0;i<128;i++){
        float4 av=a[i], wv=w[i];
        s += av.x*wv.x + av.y*wv.y + av.z*wv.z + av.w*wv.w;
    }
    float v = fmaxf(s + scale_b[h], 0.f);
    g_h[gid] = v; g_c[gid] = v;
}

__global__ void attn_kernel(const float* __restrict__ attn_W, const int* __restrict__ src)
{
    int b = blockIdx.x, tid = threadIdx.x;
    __shared__ float sc[56];
    __shared__ float aw[56];
    int w = tid >> 5, lane = tid & 31;
    for (int s = w; s < SS; s += 8){
        const float* row = g_enc_out + (size_t)(b*SS+s)*EE;
        float a = 0.f;
        for (int e = lane; e < EE; e += 32) a += row[e]*attn_W[e];
        #pragma unroll
        for (int o=16;o>0;o>>=1) a += __shfl_xor_sync(0xffffffffu, a, o);
        if (lane==0) sc[s] = a;
    }
    __syncthreads();
    if (tid == 0){
        float mx = -1e30f;
        for (int s=0;s<SS;s++) mx = fmaxf(mx, sc[s]);
        float tot = 0.f;
        for (int s=0;s<SS;s++){
            float e = (src[b*SS+s]==0) ? 0.f : expf(sc[s]-mx);
            aw[s] = e; tot += e;
        }
        float inv = 1.f/tot;
        for (int s=0;s<SS;s++) aw[s] *= inv;
    }
    __syncthreads();
    for (int e = tid; e < EE; e += blockDim.x){
        float a = 0.f;
        #pragma unroll 5
        for (int s=0;s<SS;s++) a += aw[s]*g_enc_out[(size_t)(b*SS+s)*EE + e];
        g_ctx[b*EE + e] = a;
    }
}

__global__ void gconst_kernel(const float* __restrict__ W_ih,
                              const float* __restrict__ b_ih, const float* __restrict__ b_hh)
{
    int gid = blockIdx.x*blockDim.x + threadIdx.x;
    int b = gid >> 12, j = gid & 4095;
    const float4* c4 = (const float4*)(g_ctx + b*EE);
    const float4* w4 = (const float4*)(W_ih + (size_t)j*1024 + 512);
    float s = 0.f;
    #pragma unroll 8
    for (int i=0;i<128;i++){
        float4 cv=c4[i], wv=w4[i];
        s += cv.x*wv.x + cv.y*wv.y + cv.z*wv.z + cv.w*wv.w;
    }
    g_gconst[gid] = s + b_ih[j] + b_hh[j];
}

// ============================================================
// Hoisted token-embedding GEMM for ALL steps (fp32)
// ============================================================
__global__ __launch_bounds__(256)
void dec_pre(const int* __restrict__ tgt, const float* __restrict__ dec_emb,
             const float* __restrict__ W_ih)
{
    __shared__ __align__(16) float As[128*20];
    __shared__ __align__(16) float Bs[16*132];
    const int m0 = blockIdx.x * 128;
    const int n0 = blockIdx.y * 128;
    const int tid = threadIdx.x;
    const int tx = tid & 15, ty = tid >> 4;

    ull acc[8][2][2];
    #pragma unroll
    for (int i=0;i<8;i++)
        #pragma unroll
        for (int q=0;q<2;q++){ acc[i][q][0]=0ull; acc[i][q][1]=0ull; }

    for (int kt = 0; kt < 512; kt += 16){
        #pragma unroll
        for (int l=0;l<2;l++){
            int f4 = tid + 256*l;
            int row = f4 >> 2, k4 = (f4 & 3) << 2;
            int r = m0 + row;
            int tok = tgt[(r & 63)*50 + (r >> 6)];
            float4 v = *(const float4*)(dec_emb + (size_t)tok*512 + kt + k4);
            *(float4*)(As + row*20 + k4) = v;
        }
        #pragma unroll
        for (int l=0;l<2;l++){
            int f4 = tid + 256*l;
            int row = f4 >> 2, k4 = (f4 & 3) << 2;
            float4 v = *(const float4*)(W_ih + (size_t)(n0+row)*1024 + kt + k4);
            Bs[(k4+0)*132 + row] = v.x;
            Bs[(k4+1)*132 + row] = v.y;
            Bs[(k4+2)*132 + row] = v.z;
            Bs[(k4+3)*132 + row] = v.w;
        }
        __syncthreads();
        #pragma unroll
        for (int kq=0;kq<4;kq++){
            float4 av[8];
            #pragma unroll
            for (int i=0;i<8;i++) av[i] = *(const float4*)(As + (ty*8+i)*20 + kq*4);
            #pragma unroll
            for (int kk=0;kk<4;kk++){
                ull a2[8];
                #pragma unroll
                for (int i=0;i<8;i++){
                    float a = (kk==0)?av[i].x:(kk==1)?av[i].y:(kk==2)?av[i].z:av[i].w;
                    a2[i] = dup2(a);
                }
                const int k = kq*4+kk;
                #pragma unroll
                for (int q=0;q<2;q++){
                    ulonglong2 bv = *(const ulonglong2*)(Bs + k*132 + tx*4 + q*64);
                    #pragma unroll
                    for (int i=0;i<8;i++){ ffma2(acc[i][q][0], a2[i], bv.x);
                                           ffma2(acc[i][q][1], a2[i], bv.y); }
                }
            }
        }
        __syncthreads();
    }
    #pragma unroll
    for (int i=0;i<8;i++){
        int gm = m0 + ty*8 + i;
        int b = gm & 63;
        #pragma unroll
        for (int q=0;q<2;q++){
            int gn = n0 + tx*4 + q*64;
            float2 p0 = unpk(acc[i][q][0]);
            float2 p1 = unpk(acc[i][q][1]);
            float4 gc = *(const float4*)(g_gconst + (size_t)b*G4H + gn);
            *(float4*)(g_pre + (size_t)gm*G4H + gn) =
                make_float4(p0.x+gc.x, p0.y+gc.y, p1.x+gc.z, p1.y+gc.w);
        }
    }
}

// ============================================================
// PERSISTENT fused decoder: all 49 steps in one launch.
// 256 CTAs x 128 threads; CTA = (n-tile 128 of 4096) x (k-split 128 of 1024).
// W_hh slice transposed into SMEM once; h slice staged per step; grid barrier
// between GEMM and LSTM phases. Cell state c lives in registers.
// ============================================================
#define DSM_AS 0                       /* As: 64 x 132 floats */
#define DSM_BS (64*132)                /* Bs: 128(k) x 132 floats */
#define DSM_TOT ((64*132 + 128*132)*4) /* 101376 bytes */

__global__ __launch_bounds__(128)
void decoder_persist(const float* __restrict__ W_hh)
{
    extern __shared__ __align__(16) float dsm[];
    float* As = dsm + DSM_AS;
    float* Bs = dsm + DSM_BS;
    const int cid = blockIdx.x;
    const int n0 = (cid & 31) * 128;
    const int ksplit = cid >> 5;
    const int kbase = ksplit * KCHUNK;
    const int tid = threadIdx.x;
    const int tx = tid & 15, ty = tid >> 4;
    unsigned target = g_bepoch;       // read before any arrival (safe)

    // one-time: W slice -> SMEM, transposed to Bs[k*132 + n]
    #pragma unroll 4
    for (int l = 0; l < 32; l++){
        int idx = tid + 128*l;                    // 4096 float4 tasks
        int n = idx >> 5, k4 = (idx & 31) * 4;
        float4 v = *(const float4*)(W_hh + (size_t)(n0+n)*1024 + kbase + k4);
        Bs[(k4+0)*132 + n] = v.x;
        Bs[(k4+1)*132 + n] = v.y;
        Bs[(k4+2)*132 + n] = v.z;
        Bs[(k4+3)*132 + n] = v.w;
    }

    // cell state in registers (each thread owns the same 2 gids every step)
    const int gid0 = cid*128 + tid;
    const int gid1 = gid0 + 32768;
    float creg0 = g_c[gid0];
    float creg1 = g_c[gid1];

    for (int t = 0; t < NSTEP; t++){
        // ---- stage h slice: As[m*132 + k] = g_h[m*1024 + kbase + k]
        #pragma unroll
        for (int l = 0; l < 16; l++){
            int idx = tid + 128*l;               // 2048 float4
            int m = idx >> 5, c4 = (idx & 31)*4;
            float4 v = __ldcg((const float4*)(g_h + m*1024 + kbase + c4));
            *(float4*)(As + m*132 + c4) = v;
        }
        __syncthreads();

        // ---- gates GEMM: 64m x 128n x 128k from SMEM
        ull acc[8][2][2];
        #pragma unroll
        for (int i=0;i<8;i++)
            #pragma unroll
            for (int q=0;q<2;q++){ acc[i][q][0]=0ull; acc[i][q][1]=0ull; }

        #pragma unroll 4
        for (int kq = 0; kq < 32; kq++){
            float4 av[8];
            #pragma unroll
            for (int i=0;i<8;i++) av[i] = *(const float4*)(As + (ty*8+i)*132 + kq*4);
            #pragma unroll
            for (int kk=0;kk<4;kk++){
                ull a2[8];
                #pragma unroll
                for (int i=0;i<8;i++){
                    float a = (kk==0)?av[i].x:(kk==1)?av[i].y:(kk==2)?av[i].z:av[i].w;
                    a2[i] = dup2(a);
                }
                const int k = kq*4+kk;
                #pragma unroll
                for (int q=0;q<2;q++){
                    ulonglong2 bv = *(const ulonglong2*)(Bs + k*132 + tx*4 + q*64);
                    #pragma unroll
                    for (int i=0;i<8;i++){ ffma2(acc[i][q][0], a2[i], bv.x);
                                           ffma2(acc[i][q][1], a2[i], bv.y); }
                }
            }
        }
        {
            float* outp = g_part + (size_t)ksplit*(BB*G4H);
            #pragma unroll
            for (int i=0;i<8;i++){
                int m = ty*8 + i;
                #pragma unroll
                for (int q=0;q<2;q++){
                    int n = n0 + tx*4 + q*64;
                    float2 p0 = unpk(acc[i][q][0]);
                    float2 p1 = unpk(acc[i][q][1]);
                    *(float4*)(outp + (size_t)m*G4H + n) =
                        make_float4(p0.x, p0.y, p1.x, p1.y);
                }
            }
        }
        __syncthreads();          // SMEM As reuse safety before next stage (post-barrier)
        gbar(target);

        // ---- LSTM pointwise: 2 elems per thread (fixed mapping)
        #pragma unroll
        for (int e = 0; e < 2; e++){
            int gid = (e==0) ? gid0 : gid1;
            int b = gid >> 10, h = gid & 1023;
            size_t prow = (size_t)(t*64 + b)*G4H;
            float gi = g_pre[prow + h];
            float gf = g_pre[prow + 1024 + h];
            float gg = g_pre[prow + 2048 + h];
            float go = g_pre[prow + 3072 + h];
            int base = b*G4H;
            #pragma unroll
            for (int s=0;s<KSPLIT;s++){
                const float* p = g_part + (size_t)s*(BB*G4H) + base;
                gi += __ldcg(p + h);
                gf += __ldcg(p + 1024 + h);
                gg += __ldcg(p + 2048 + h);
                go += __ldcg(p + 3072 + h);
            }
            float c = (e==0) ? creg0 : creg1;
            float ii = 1.f/(1.f+expf(-gi));
            float ff = 1.f/(1.f+expf(-gf));
            float oo = 1.f/(1.f+expf(-go));
            float gt = tanhf(gg);
            float cn = ff*c + ii*gt;
            float hn = oo*tanhf(cn);
            if (e==0) creg0 = cn; else creg1 = cn;
            g_h[gid] = hn;
            g_Ah[(size_t)(t*64 + b)*KA + h] = __float2half_rn(hn);
        }
        gbar(target);
    }
}

// ============================================================
// Fallback per-step kernels (used only if persistent residency check fails)
// ============================================================
__global__ __launch_bounds__(128)
void gates_gemm(const float* __restrict__ W_hh)
{
    __shared__ __align__(16) float As[64*20];
    __shared__ __align__(16) float Bs[16*132];
    const int n0 = blockIdx.x * 128;
    const int kbase = blockIdx.y * KCHUNK;
    const int tid = threadIdx.x;
    const int tx = tid & 15, ty = tid >> 4;

    ull acc[8][2][2];
    #pragma unroll
    for (int i=0;i<8;i++)
        #pragma unroll
        for (int q=0;q<2;q++){ acc[i][q][0]=0ull; acc[i][q][1]=0ull; }

    for (int kt = 0; kt < KCHUNK; kt += 16){
        const int kg0 = kbase + kt;
        #pragma unroll
        for (int l=0;l<2;l++){
            int f4 = tid + 128*l;
            int row = f4 >> 2, k4 = (f4 & 3) << 2;
            float4 v = *(const float4*)(g_h + row*1024 + kg0 + k4);
            *(float4*)(As + row*20 + k4) = v;
        }
        #pragma unroll
        for (int l=0;l<4;l++){
            int f4 = tid + 128*l;
            int row = f4 >> 2, k4 = (f4 & 3) << 2;
            float4 v = *(const float4*)(W_hh + (size_t)(n0+row)*1024 + kg0 + k4);
            Bs[(k4+0)*132 + row] = v.x;
            Bs[(k4+1)*132 + row] = v.y;
            Bs[(k4+2)*132 + row] = v.z;
            Bs[(k4+3)*132 + row] = v.w;
        }
        __syncthreads();
        #pragma unroll
        for (int kq=0;kq<4;kq++){
            float4 av[8];
            #pragma unroll
            for (int i=0;i<8;i++) av[i] = *(const float4*)(As + (ty*8+i)*20 + kq*4);
            #pragma unroll
            for (int kk=0;kk<4;kk++){
                ull a2[8];
                #pragma unroll
                for (int i=0;i<8;i++){
                    float a = (kk==0)?av[i].x:(kk==1)?av[i].y:(kk==2)?av[i].z:av[i].w;
                    a2[i] = dup2(a);
                }
                const int k = kq*4+kk;
                #pragma unroll
                for (int q=0;q<2;q++){
                    ulonglong2 bv = *(const ulonglong2*)(Bs + k*132 + tx*4 + q*64);
                    #pragma unroll
                    for (int i=0;i<8;i++){ ffma2(acc[i][q][0], a2[i], bv.x);
                                           ffma2(acc[i][q][1], a2[i], bv.y); }
                }
            }
        }
        __syncthreads();
    }
    float* outp = g_part + (size_t)blockIdx.y*(BB*G4H);
    #pragma unroll
    for (int i=0;i<8;i++){
        int m = ty*8 + i;
        #pragma unroll
        for (int q=0;q<2;q++){
            int n = n0 + tx*4 + q*64;
            float2 p0 = unpk(acc[i][q][0]);
            float2 p1 = unpk(acc[i][q][1]);
            *(float4*)(outp + (size_t)m*G4H + n) = make_float4(p0.x, p0.y, p1.x, p1.y);
        }
    }
}

__global__ void lstm_pw(int t)
{
    int gid = blockIdx.x*blockDim.x + threadIdx.x;
    int b = gid >> 10, h = gid & 1023;
    size_t prow = (size_t)(t*64 + b)*G4H;
    float gi = g_pre[prow + h];
    float gf = g_pre[prow + 1024 + h];
    float gg = g_pre[prow + 2048 + h];
    float go = g_pre[prow + 3072 + h];
    int base = b*G4H;
    #pragma unroll
    for (int s=0;s<KSPLIT;s++){
        const float* p = g_part + (size_t)s*(BB*G4H) + base;
        gi += p[h]; gf += p[1024+h]; gg += p[2048+h]; go += p[3072+h];
    }
    float c  = g_c[gid];
    float ii = 1.f/(1.f+expf(-gi));
    float ff = 1.f/(1.f+expf(-gf));
    float oo = 1.f/(1.f+expf(-go));
    float gt = tanhf(gg);
    float cn = ff*c + ii*gt;
    float hn = oo*tanhf(cn);
    g_c[gid] = cn; g_h[gid] = hn;
    g_Ah[(size_t)(t*64 + b)*KA + h] = __float2half_rn(hn);
}

// ============================================================
// proj_W fp32 -> fp16
// ============================================================
__global__ __launch_bounds__(256)
void conv_w(const float* __restrict__ W)
{
    size_t i = (size_t)blockIdx.x*blockDim.x + threadIdx.x;
    float4 v = ((const float4*)W)[i];
    __half h0 = __float2half_rn(v.x);
    __half h1 = __float2half_rn(v.y);
    __half h2 = __float2half_rn(v.z);
    __half h3 = __float2half_rn(v.w);
    ull packed;
    asm("mov.b64 %0, {%1,%2,%3,%4};" : "=l"(packed)
        : "h"(*(unsigned short*)&h0), "h"(*(unsigned short*)&h1),
          "h"(*(unsigned short*)&h2), "h"(*(unsigned short*)&h3));
    *(ull*)(g_Bh + i*4) = packed;
}

// ============================================================
// Projection via mma.sync fp16: out = A(3200x1024) . B(32000x1024)^T + bias
// CTA 128m x 256n, 8 warps (4M x 2N), 4-stage cp.async pipeline.
// ============================================================
#define NSTG 4
#define TSTA 10240              /* 128 rows * 80 B */
#define TSTB 20480              /* 256 rows * 80 B */
#define SM_PROJ (NSTG*(TSTA+TSTB))  /* 122880 */
#define NKS (KA/32)             /* 32 k-chunks */

__global__ __launch_bounds__(256)
void proj_mma(float* __restrict__ out, const float* __restrict__ bias)
{
    extern __shared__ __align__(16) char sm[];
    const uint32_t uA = smem_u32(sm);
    const uint32_t uB = uA + NSTG*TSTA;
    const int tid = threadIdx.x;
    const int wid = tid >> 5, lane = tid & 31;
    const int m0 = blockIdx.x * 128;
    const int n0 = blockIdx.y * 256;
    const int wm = wid & 3, wn = wid >> 2;

    float acc[2][16][4];
    #pragma unroll
    for (int a=0;a<2;a++)
        #pragma unroll
        for (int j=0;j<16;j++)
            #pragma unroll
            for (int x=0;x<4;x++) acc[a][j][x] = 0.f;

    const __half* gA = g_Ah + (size_t)m0*KA;
    const __half* gB = g_Bh + (size_t)n0*KA;

    auto load_stage = [&](int slot, int ks){
        int k0 = ks * 32;
        uint32_t sA = uA + slot*TSTA;
        uint32_t sB = uB + slot*TSTB;
        #pragma unroll
        for (int i = 0; i < 2; i++){
            int idx = tid + 256*i;        // 512 chunks: 128 rows x 4
            int row = idx >> 2, lc = idx & 3;
            cpasync16(sA + row*80 + lc*16, gA + (size_t)row*KA + k0 + lc*8);
        }
        #pragma unroll
        for (int i = 0; i < 4; i++){
            int idx = tid + 256*i;        // 1024 chunks: 256 rows x 4
            int row = idx >> 2, lc = idx & 3;
            cpasync16(sB + row*80 + lc*16, gB + (size_t)row*KA + k0 + lc*8);
        }
        cp_commit();
    };

    load_stage(0, 0);
    load_stage(1, 1);
    load_stage(2, 2);

    const int g  = lane >> 3;
    const int lr = lane & 7;

    for (int ks = 0; ks < NKS; ks++){
        asm volatile("cp.async.wait_group 2;");
        __syncthreads();
        int ld = ks + NSTG - 1;
        if (ld < NKS) load_stage(ld & (NSTG-1), ld);
        else cp_commit();

        const uint32_t bufA = uA + (ks & (NSTG-1))*TSTA;
        const uint32_t bufB = uB + (ks & (NSTG-1))*TSTB;

        #pragma unroll
        for (int kk = 0; kk < 32; kk += 16){
            uint32_t afr[2][4];
            #pragma unroll
            for (int mi = 0; mi < 2; mi++){
                int row = wm*32 + mi*16 + ((g & 1) ? 8 : 0) + lr;
                int kof = kk + (g >> 1)*8;
                ldm4(afr[mi], bufA + row*80 + kof*2);
            }
            uint32_t bfr[8][4];
            #pragma unroll
            for (int p = 0; p < 8; p++){
                int row = wn*128 + p*16 + (g >> 1)*8 + lr;
                int kof = kk + (g & 1)*8;
                ldm4(bfr[p], bufB + row*80 + kof*2);
            }
            #pragma unroll
            for (int mi = 0; mi < 2; mi++)
                #pragma unroll
                for (int j = 0; j < 16; j++){
                    int p = j >> 1, h2 = (j & 1)*2;
                    mma16816h(acc[mi][j], afr[mi], bfr[p][h2], bfr[p][h2+1]);
                }
        }
        __syncthreads();
    }

    // ---- epilogue ----
    const int tm = lane >> 2;
    const int tn = (lane & 3)*2;
    #pragma unroll
    for (int mi = 0; mi < 2; mi++){
        #pragma unroll
        for (int j = 0; j < 16; j++){
            int gn = n0 + wn*128 + j*8 + tn;
            float2 bb = *(const float2*)(bias + gn);
            int gm0 = m0 + wm*32 + mi*16 + tm;
            if (gm0 < MPROJ){
                float2 o; o.x = acc[mi][j][0] + bb.x; o.y = acc[mi][j][1] + bb.y;
                *(float2*)(out + (size_t)gm0*VTS + gn) = o;
            }
            int gm1 = gm0 + 8;
            if (gm1 < MPROJ){
                float2 o; o.x = acc[mi][j][2] + bb.x; o.y = acc[mi][j][3] + bb.y;
                *(float2*)(out + (size_t)gm1*VTS + gn) = o;
            }
        }
    }
}

// ============================================================
extern "C" void kernel_launch(void* const* d_in, const int* in_sizes, int n_in,
                              void* d_out, int out_size)
{
    const int*   src      = (const int*)  d_in[0];
    const int*   pos      = (const int*)  d_in[2];
    const int*   tgt      = (const int*)  d_in[3];
    const float* enc_emb  = (const float*)d_in[4];
    const float* pos_emb  = (const float*)d_in[5];
    const float* cat_W    = (const float*)d_in[6];
    const float* cat_b    = (const float*)d_in[7];
    const float* scale_W  = (const float*)d_in[8];
    const float* scale_b  = (const float*)d_in[9];
    const float* dec_emb  = (const float*)d_in[10];
    const float* attn_W   = (const float*)d_in[11];
    const float* W_ih     = (const float*)d_in[13];
    const float* W_hh     = (const float*)d_in[14];
    const float* b_ih     = (const float*)d_in[15];
    const float* b_hh     = (const float*)d_in[16];
    const float* proj_W   = (const float*)d_in[17];
    const float* proj_b   = (const float*)d_in[18];
    float* out = (float*)d_out;

    cudaFuncSetAttribute(proj_mma, cudaFuncAttributeMaxDynamicSharedMemorySize, SM_PROJ);
    cudaFuncSetAttribute(decoder_persist, cudaFuncAttributeMaxDynamicSharedMemorySize, DSM_TOT);

    // Residency check for the persistent decoder (deadlock-proof fallback)
    int per_sm = 0, n_sm = 0;
    cudaOccupancyMaxActiveBlocksPerMultiprocessor(&per_sm, decoder_persist, 128, DSM_TOT);
    cudaDeviceGetAttribute(&n_sm, cudaDevAttrMultiProcessorCount, 0);
    const bool persistent_ok = ((long)per_sm * n_sm >= DCTA);

    // B conversion
    conv_w<<<32000, 256>>>(proj_W);

    // Encoder
    enc_gemm<<<dim3(25,4), 256>>>(src, pos, enc_emb, pos_emb, cat_W, cat_b);
    avg_kernel<<<64, 512>>>();
    h0_kernel<<<256, 256>>>(scale_W, scale_b);

    // Loop-invariant attention context + hoisted per-step constants
    attn_kernel<<<64, 256>>>(attn_W, src);
    gconst_kernel<<<1024, 256>>>(W_ih, b_ih, b_hh);
    dec_pre<<<dim3(25,32), 256>>>(tgt, dec_emb, W_ih);

    // Recurrence
    if (persistent_ok){
        decoder_persist<<<DCTA, 128, DSM_TOT>>>(W_hh);
    } else {
        for (int t = 0; t < NSTEP; t++){
            gates_gemm<<<dim3(32, KSPLIT), 128>>>(W_hh);
            lstm_pw<<<256, 256>>>(t);
        }
    }

    // Single fp16 tensor-core projection (K=1024, 128x256 tiles)
    proj_mma<<<dim3(25,125), 256, SM_PROJ>>>(out, proj_b);
}